// round 14
// baseline (speedup 1.0000x reference)
#include <cuda_runtime.h>
#include <cuda_fp16.h>
#include <cstdint>
#include <math.h>

// ---------------- problem constants ----------------
#define T_TOK 8192
#define DIMD  1024
#define DIMH  2048
#define NEXP  8
#define NITEM (T_TOK*2)
#define NBLK_DISP 64
#define MARGIN_TAU 1e-3f

// ---------------- scratch (device globals) ----------------
__device__ float  g_h1[(size_t)T_TOK * DIMH];           // gate hidden fp32; reused as repair buffer
__device__ __half g_hs[(size_t)T_TOK * DIMH];           // shared-expert hidden fp16
__device__ __half g_he[(size_t)NITEM * DIMH];           // routed hidden fp16 (compact)
__device__ __half g_ho[(size_t)NITEM * DIMD];           // routed out rows fp16 (weighted, compact)
__device__ __half g_xhi[(size_t)T_TOK * DIMD];
__device__ __half g_Bg1h[(size_t)DIMD * DIMH];          // gw1 fp16 (row-major [K,N])
__device__ __half g_Bs1h[(size_t)DIMD * DIMH];          // Ws1 fp16
__device__ __half g_Bs2h[(size_t)DIMH * DIMD];          // Ws2 fp16
__device__ __half g_Be1h[(size_t)NEXP * DIMD * DIMH];   // We1 fp16
__device__ __half g_Be2h[(size_t)NEXP * DIMH * DIMD];   // We2 fp16
__device__ int    g_topk_idx[NITEM];
__device__ float  g_topk_w[NITEM];
__device__ int    g_list[NITEM];
__device__ float  g_wlist[NITEM];
__device__ int    g_slot[NITEM];                        // item -> compact slot
__device__ int    g_cnt[NEXP];
__device__ int    g_base[NEXP];
__device__ int    g_mblkBase[NEXP + 1];
__device__ int    g_blockCnt[NBLK_DISP * NEXP];
__device__ int    g_blockOff[NBLK_DISP * NEXP];
__device__ int    g_fixCnt;
__device__ int    g_fixList[T_TOK];

// ---------------- small helpers (defined BEFORE use) ----------------
__device__ __forceinline__ uint32_t h2_as_u32(__half2 h) {
    return *reinterpret_cast<uint32_t*>(&h);
}
__device__ __forceinline__ uint32_t smem_u32(const void* p) {
    uint32_t a;
    asm("{ .reg .u64 t; cvta.to.shared.u64 t, %1; cvt.u32.u64 %0, t; }" : "=r"(a) : "l"(p));
    return a;
}
__device__ __forceinline__ void ldsm4(uint32_t& r0, uint32_t& r1, uint32_t& r2, uint32_t& r3, uint32_t a) {
    asm volatile("ldmatrix.sync.aligned.m8n8.x4.shared.b16 {%0,%1,%2,%3}, [%4];"
                 : "=r"(r0), "=r"(r1), "=r"(r2), "=r"(r3) : "r"(a));
}
__device__ __forceinline__ void ldsm4t(uint32_t& r0, uint32_t& r1, uint32_t& r2, uint32_t& r3, uint32_t a) {
    asm volatile("ldmatrix.sync.aligned.m8n8.x4.trans.shared.b16 {%0,%1,%2,%3}, [%4];"
                 : "=r"(r0), "=r"(r1), "=r"(r2), "=r"(r3) : "r"(a));
}
__device__ __forceinline__ void mma16816(float* d, const uint32_t* a, const uint32_t* b) {
    asm volatile("mma.sync.aligned.m16n8k16.row.col.f32.f16.f16.f32 "
                 "{%0,%1,%2,%3},{%4,%5,%6,%7},{%8,%9},{%0,%1,%2,%3};"
                 : "+f"(d[0]), "+f"(d[1]), "+f"(d[2]), "+f"(d[3])
                 : "r"(a[0]), "r"(a[1]), "r"(a[2]), "r"(a[3]), "r"(b[0]), "r"(b[1]));
}
#define CP_ASYNC16(sa, ga) asm volatile("cp.async.cg.shared.global [%0], [%1], 16;" :: "r"(sa), "l"(ga))
#define CP_COMMIT()        asm volatile("cp.async.commit_group;" ::: "memory")
template<int N> __device__ __forceinline__ void cp_wait() {
    asm volatile("cp.async.wait_group %0;" :: "n"(N) : "memory");
}

// ---------------- activations ----------------
__device__ __forceinline__ float gelu_erf(float v) {
    return 0.5f * v * (1.0f + erff(v * 0.70710678118654752f));
}
__device__ __forceinline__ float gelu_tanh(float v) {
    float u = 0.7978845608028654f * (v + 0.044715f * v * v * v);
    float t = __expf(2.0f * u);
    float th = 1.0f - __fdividef(2.0f, t + 1.0f);
    return 0.5f * v * (1.0f + th);
}

// ---------------- conversions (pure streaming, no transpose) ----------------
__global__ void cvt_hi(const float* __restrict__ src, __half* __restrict__ hi, int n8) {
    int i = blockIdx.x * blockDim.x + threadIdx.x;
    if (i == 0) g_fixCnt = 0;                           // fused reset
    if (i >= n8) return;
    float4 v0 = reinterpret_cast<const float4*>(src)[2 * i];
    float4 v1 = reinterpret_cast<const float4*>(src)[2 * i + 1];
    uint4 o;
    o.x = h2_as_u32(__halves2half2(__float2half_rn(v0.x), __float2half_rn(v0.y)));
    o.y = h2_as_u32(__halves2half2(__float2half_rn(v0.z), __float2half_rn(v0.w)));
    o.z = h2_as_u32(__halves2half2(__float2half_rn(v1.x), __float2half_rn(v1.y)));
    o.w = h2_as_u32(__halves2half2(__float2half_rn(v1.z), __float2half_rn(v1.w)));
    reinterpret_cast<uint4*>(hi)[i] = o;
}

__global__ void cvt_w(const float* __restrict__ src, __half* __restrict__ dst, int n8) {
    int i = blockIdx.x * blockDim.x + threadIdx.x;
    if (i >= n8) return;
    float4 v0 = reinterpret_cast<const float4*>(src)[2 * i];
    float4 v1 = reinterpret_cast<const float4*>(src)[2 * i + 1];
    uint4 o;
    o.x = h2_as_u32(__halves2half2(__float2half_rn(v0.x), __float2half_rn(v0.y)));
    o.y = h2_as_u32(__halves2half2(__float2half_rn(v0.z), __float2half_rn(v0.w)));
    o.z = h2_as_u32(__halves2half2(__float2half_rn(v1.x), __float2half_rn(v1.y)));
    o.w = h2_as_u32(__halves2half2(__float2half_rn(v1.z), __float2half_rn(v1.w)));
    reinterpret_cast<uint4*>(dst)[i] = o;
}

// ---------------- fp16 tensor GEMM: CTA 128x128, BK=64, 3-stage cp.async (R7 config) ----------------
// A row-major [M,K] (ldsm non-trans); B row-major [K,N] (ldsm.trans)
// MODE 0: dense A rows; 1: gather A rows via g_list (expert blocks); 2: dense compact A
// ACT 0: none, 1: gelu_erf, 2: gelu_tanh
// OUT 0: fp32 store; 1: fp16 store; 3: weighted fp16 store to compact row (base+m);
//     4: fp32 store + fused routed combine (out = v + ho[slot0] + ho[slot1], ho fp16)
#define ROWPAD_A 144
#define ROWPAD_B 272
#define TILE_A (128 * ROWPAD_A)       // 18432 B
#define TILE_B (64 * ROWPAD_B)        // 17408 B
#define STAGE_E (TILE_A + TILE_B)     // 35840 B
#define SME_BYTES (3 * STAGE_E)       // 107520 B

template<int MODE, int ACT, int OUT>
__global__ __launch_bounds__(256, 2)
void gemm_f16(const __half* __restrict__ A, const __half* __restrict__ B,
              const float* __restrict__ bias, void* __restrict__ Cv,
              int K, int ldn)
{
    int e = 0, m0, base = 0, cnt = 0;
    if (MODE == 0) {
        m0 = blockIdx.x * 128;
    } else {
        if ((int)blockIdx.x >= g_mblkBase[NEXP]) return;
#pragma unroll
        for (int i = 1; i < NEXP; i++) if ((int)blockIdx.x >= g_mblkBase[i]) e = i;
        m0 = ((int)blockIdx.x - g_mblkBase[e]) * 128;
        base = g_base[e]; cnt = g_cnt[e];
        B    += (size_t)e * K * ldn;
        bias += (size_t)e * ldn;
    }
    const int n0 = blockIdx.y * 128;

    extern __shared__ char smem[];
    const uint32_t sbase = smem_u32(smem);
    const int tid = threadIdx.x, lane = tid & 31, wid = tid >> 5;

    const int larow = tid >> 3;
    const uint32_t dstA = (uint32_t)(larow * ROWPAD_A + (tid & 7) * 16);
    const __half* aptr[4];
#pragma unroll
    for (int i = 0; i < 4; i++) {
        int m = m0 + larow + 32 * i;
        if (MODE == 0)      aptr[i] = A + (size_t)m * K;
        else if (MODE == 1) { int mm = (m < cnt) ? m : 0; aptr[i] = A + (size_t)g_list[base + mm] * K; }
        else                { int mm = (m < cnt) ? m : 0; aptr[i] = A + (size_t)(base + mm) * K; }
        aptr[i] += (tid & 7) * 8;
    }
    const int lbrow = tid >> 4;
    const uint32_t dstB = (uint32_t)(lbrow * ROWPAD_B + (tid & 15) * 16);
    const __half* bptr[4];
#pragma unroll
    for (int i = 0; i < 4; i++)
        bptr[i] = B + (size_t)(lbrow + 16 * i) * ldn + n0 + (tid & 15) * 8;

    const int S = K >> 6;
    auto issue = [&](int s) {
        uint32_t st = sbase + (uint32_t)((s % 3) * STAGE_E);
#pragma unroll
        for (int i = 0; i < 4; i++)
            CP_ASYNC16(st + dstA + (uint32_t)(32 * i * ROWPAD_A), (const void*)(aptr[i] + s * 64));
#pragma unroll
        for (int i = 0; i < 4; i++)
            CP_ASYNC16(st + TILE_A + dstB + (uint32_t)(16 * i * ROWPAD_B), (const void*)(bptr[i] + (size_t)s * 64 * ldn));
        CP_COMMIT();
    };
    issue(0);
    if (S > 1) issue(1);

    const int wm0 = (wid >> 1) * 32;
    const int wn0 = (wid & 1) * 64;
    const int arow_l = (lane & 7) + ((lane >> 3) & 1) * 8;
    const int acol_l = (lane >> 4) * 8;
    const int bkrow_l = (lane & 7) + ((lane >> 3) & 1) * 8;
    const int bncol_l = (lane >> 4) * 8;

    float acc[2][8][4];
#pragma unroll
    for (int i = 0; i < 2; i++)
#pragma unroll
        for (int j = 0; j < 8; j++)
#pragma unroll
            for (int q = 0; q < 4; q++) acc[i][j][q] = 0.f;

    for (int s = 0; s < S; s++) {
        if (s + 1 < S) cp_wait<1>(); else cp_wait<0>();
        __syncthreads();
        if (s + 2 < S) issue(s + 2);

        const uint32_t st = sbase + (uint32_t)((s % 3) * STAGE_E);
        const uint32_t sA = st, sB = st + TILE_A;
#pragma unroll
        for (int ks = 0; ks < 4; ks++) {
            const int k0 = ks * 16;
            uint32_t a[2][4], b[4][4];
#pragma unroll
            for (int mf = 0; mf < 2; mf++)
                ldsm4(a[mf][0], a[mf][1], a[mf][2], a[mf][3],
                      sA + (uint32_t)((wm0 + mf * 16 + arow_l) * ROWPAD_A + (k0 + acol_l) * 2));
#pragma unroll
            for (int p = 0; p < 4; p++)
                ldsm4t(b[p][0], b[p][1], b[p][2], b[p][3],
                       sB + (uint32_t)((k0 + bkrow_l) * ROWPAD_B + (wn0 + p * 16 + bncol_l) * 2));
#pragma unroll
            for (int mf = 0; mf < 2; mf++)
#pragma unroll
                for (int nf = 0; nf < 8; nf++)
                    mma16816(acc[mf][nf], a[mf], &b[nf >> 1][(nf & 1) * 2]);
        }
    }

    // ---- epilogue ----
    const int tr = lane >> 2, tc = (lane & 3) * 2;
#pragma unroll
    for (int mf = 0; mf < 2; mf++) {
#pragma unroll
        for (int half_ = 0; half_ < 2; half_++) {
            const int m = m0 + wm0 + mf * 16 + tr + half_ * 8;
            bool ok = (MODE == 0) || (m < cnt);
            if (!ok) continue;
            int orow = m; float wgt = 1.f;
            int s0 = 0, s1 = 0;
            if (MODE == 1) orow = base + m;
            if (MODE == 2) {
                if (OUT == 3) { orow = base + m; wgt = g_wlist[base + m]; }
                else          { orow = g_list[base + m]; wgt = g_wlist[base + m]; }
            }
            if (OUT == 4) { s0 = g_slot[2 * m]; s1 = g_slot[2 * m + 1]; }
#pragma unroll
            for (int nf = 0; nf < 8; nf++) {
                const int c = n0 + wn0 + nf * 8 + tc;
                float v0 = acc[mf][nf][half_ * 2 + 0] + bias[c];
                float v1 = acc[mf][nf][half_ * 2 + 1] + bias[c + 1];
                if (ACT == 1) { v0 = gelu_erf(v0);  v1 = gelu_erf(v1); }
                if (ACT == 2) { v0 = gelu_tanh(v0); v1 = gelu_tanh(v1); }
                if (OUT == 0) {
                    float2 w2; w2.x = v0; w2.y = v1;
                    *reinterpret_cast<float2*>((float*)Cv + (size_t)orow * ldn + c) = w2;
                } else if (OUT == 1) {
                    *reinterpret_cast<__half2*>((__half*)Cv + (size_t)orow * ldn + c) =
                        __halves2half2(__float2half_rn(v0), __float2half_rn(v1));
                } else if (OUT == 3) {
                    *reinterpret_cast<__half2*>((__half*)Cv + (size_t)orow * ldn + c) =
                        __halves2half2(__float2half_rn(wgt * v0), __float2half_rn(wgt * v1));
                } else { // OUT == 4: fused routed combine (ho fp16)
                    float2 r0 = __half22float2(*reinterpret_cast<const __half2*>(g_ho + (size_t)s0 * DIMD + c));
                    float2 r1 = __half22float2(*reinterpret_cast<const __half2*>(g_ho + (size_t)s1 * DIMD + c));
                    float2 w2; w2.x = v0 + r0.x + r1.x; w2.y = v1 + r0.y + r1.y;
                    *reinterpret_cast<float2*>((float*)Cv + (size_t)orow * ldn + c) = w2;
                }
            }
        }
    }
}

// ---------------- fp32 repair SGEMM: gathered rows (g_fixList), gelu_erf, compact out ----------------
__global__ __launch_bounds__(256, 2)
void sgemm_fix(const float* __restrict__ A, const float* __restrict__ B,
               const float* __restrict__ bias, float* __restrict__ C)
{
    const int cnt = g_fixCnt;
    const int m0 = blockIdx.x * 128;
    if (m0 >= cnt) return;
    const int n0 = blockIdx.y * 128;
    const int K = DIMD, N = DIMH;

    __shared__ float As[8][128];
    __shared__ float Bs[8][128];
    const int tid = threadIdx.x;
    const int aRow = tid >> 1, aCol = (tid & 1) * 4;
    const int bRow = tid >> 5, bCol = (tid & 31) * 4;

    int mA = m0 + aRow;
    int mm = (mA < cnt) ? mA : 0;
    const float* Arow = A + (size_t)g_fixList[mm] * K;
    const float* Bp = B + (size_t)bRow * N + n0 + bCol;

    const int ty = tid >> 4, tx = tid & 15;
    float acc[8][8];
#pragma unroll
    for (int i = 0; i < 8; i++)
#pragma unroll
        for (int j = 0; j < 8; j++) acc[i][j] = 0.f;

    for (int k0 = 0; k0 < K; k0 += 8) {
        float4 av = *reinterpret_cast<const float4*>(Arow + k0 + aCol);
        As[aCol + 0][aRow] = av.x; As[aCol + 1][aRow] = av.y;
        As[aCol + 2][aRow] = av.z; As[aCol + 3][aRow] = av.w;
        *reinterpret_cast<float4*>(&Bs[bRow][bCol]) = *reinterpret_cast<const float4*>(Bp + (size_t)k0 * N);
        __syncthreads();
#pragma unroll
        for (int kk = 0; kk < 8; kk++) {
            float4 a0 = *reinterpret_cast<const float4*>(&As[kk][ty * 8]);
            float4 a1 = *reinterpret_cast<const float4*>(&As[kk][ty * 8 + 4]);
            float4 b0 = *reinterpret_cast<const float4*>(&Bs[kk][tx * 8]);
            float4 b1 = *reinterpret_cast<const float4*>(&Bs[kk][tx * 8 + 4]);
            float a[8] = {a0.x, a0.y, a0.z, a0.w, a1.x, a1.y, a1.z, a1.w};
            float b[8] = {b0.x, b0.y, b0.z, b0.w, b1.x, b1.y, b1.z, b1.w};
#pragma unroll
            for (int i = 0; i < 8; i++)
#pragma unroll
                for (int j = 0; j < 8; j++)
                    acc[i][j] = fmaf(a[i], b[j], acc[i][j]);
        }
        __syncthreads();
    }
    const int cRow0 = m0 + ty * 8, cCol0 = n0 + tx * 8;
#pragma unroll
    for (int i = 0; i < 8; i++) {
        int m = cRow0 + i;
        if (m >= cnt) continue;
#pragma unroll
        for (int j = 0; j < 8; j++)
            C[(size_t)m * N + cCol0 + j] = gelu_erf(acc[i][j] + bias[cCol0 + j]);
    }
}

// ---------------- logits: VECTORIZED (float4 h, MLP-deep) + softmax + top-2 + margin flag ----------------
__global__ void logits_topk(const float* __restrict__ h1,
                            const float* __restrict__ gw2,
                            const float* __restrict__ gb2)
{
    __shared__ float red[8][NEXP];
    const int t = blockIdx.x;
    const float4* hrow4 = reinterpret_cast<const float4*>(h1 + (size_t)t * DIMH);
    float acc[NEXP];
#pragma unroll
    for (int j = 0; j < NEXP; j++) acc[j] = 0.f;
    // DIMH/4 = 512 float4s; 256 threads -> 2 iterations, each with 1 h-load + 8 w-loads (all independent)
#pragma unroll
    for (int it = 0; it < 2; it++) {
        const int i4 = threadIdx.x + it * 256;
        float4 h4 = hrow4[i4];
        const float4* w = reinterpret_cast<const float4*>(gw2 + (size_t)(4 * i4) * NEXP);
        float4 w0 = w[0], w1 = w[1];   // row 4*i4
        float4 w2 = w[2], w3 = w[3];   // row 4*i4+1
        float4 w4 = w[4], w5 = w[5];   // row 4*i4+2
        float4 w6 = w[6], w7 = w[7];   // row 4*i4+3
        acc[0] = fmaf(h4.x, w0.x, fmaf(h4.y, w2.x, fmaf(h4.z, w4.x, fmaf(h4.w, w6.x, acc[0]))));
        acc[1] = fmaf(h4.x, w0.y, fmaf(h4.y, w2.y, fmaf(h4.z, w4.y, fmaf(h4.w, w6.y, acc[1]))));
        acc[2] = fmaf(h4.x, w0.z, fmaf(h4.y, w2.z, fmaf(h4.z, w4.z, fmaf(h4.w, w6.z, acc[2]))));
        acc[3] = fmaf(h4.x, w0.w, fmaf(h4.y, w2.w, fmaf(h4.z, w4.w, fmaf(h4.w, w6.w, acc[3]))));
        acc[4] = fmaf(h4.x, w1.x, fmaf(h4.y, w3.x, fmaf(h4.z, w5.x, fmaf(h4.w, w7.x, acc[4]))));
        acc[5] = fmaf(h4.x, w1.y, fmaf(h4.y, w3.y, fmaf(h4.z, w5.y, fmaf(h4.w, w7.y, acc[5]))));
        acc[6] = fmaf(h4.x, w1.z, fmaf(h4.y, w3.z, fmaf(h4.z, w5.z, fmaf(h4.w, w7.z, acc[6]))));
        acc[7] = fmaf(h4.x, w1.w, fmaf(h4.y, w3.w, fmaf(h4.z, w5.w, fmaf(h4.w, w7.w, acc[7]))));
    }
    const int lane = threadIdx.x & 31, wid = threadIdx.x >> 5;
#pragma unroll
    for (int j = 0; j < NEXP; j++)
#pragma unroll
        for (int o = 16; o > 0; o >>= 1)
            acc[j] += __shfl_down_sync(0xffffffffu, acc[j], o);
    if (lane == 0) {
#pragma unroll
        for (int j = 0; j < NEXP; j++) red[wid][j] = acc[j];
    }
    __syncthreads();
    if (threadIdx.x == 0) {
        float l[NEXP];
#pragma unroll
        for (int j = 0; j < NEXP; j++) {
            l[j] = gb2[j];
#pragma unroll
            for (int w = 0; w < 8; w++) l[j] += red[w][j];
        }
        float mx = l[0];
#pragma unroll
        for (int j = 1; j < NEXP; j++) mx = fmaxf(mx, l[j]);
        float p[NEXP], s = 0.f;
#pragma unroll
        for (int j = 0; j < NEXP; j++) { p[j] = expf(l[j] - mx); s += p[j]; }
        float inv = 1.0f / s;
#pragma unroll
        for (int j = 0; j < NEXP; j++) p[j] *= inv;
        int i0 = 0;
#pragma unroll
        for (int j = 1; j < NEXP; j++) if (p[j] > p[i0]) i0 = j;
        int i1 = (i0 == 0) ? 1 : 0;
#pragma unroll
        for (int j = 0; j < NEXP; j++) if (j != i0 && p[j] > p[i1]) i1 = j;
        g_topk_idx[t * 2 + 0] = i0;  g_topk_w[t * 2 + 0] = p[i0];
        g_topk_idx[t * 2 + 1] = i1;  g_topk_w[t * 2 + 1] = p[i1];
        float p2 = -1.f;
#pragma unroll
        for (int j = 0; j < NEXP; j++)
            if (j != i0 && j != i1 && p[j] > p2) p2 = p[j];
        if (p[i1] - p2 < MARGIN_TAU) {
            int ix = atomicAdd(&g_fixCnt, 1);
            g_fixList[ix] = t;
        }
    }
}

// ---------------- repair: exact fp32 logits for flagged tokens ----------------
__global__ void repair_logits(const float* __restrict__ hf,
                              const float* __restrict__ gw2,
                              const float* __restrict__ gb2)
{
    __shared__ float red[8][NEXP];
    for (int r = blockIdx.x; r < g_fixCnt; r += gridDim.x) {
        const int t = g_fixList[r];
        const float* hrow = hf + (size_t)r * DIMH;
        float acc[NEXP];
#pragma unroll
        for (int j = 0; j < NEXP; j++) acc[j] = 0.f;
        for (int i = threadIdx.x; i < DIMH; i += 256) {
            float h = hrow[i];
            float4 w0 = *reinterpret_cast<const float4*>(gw2 + (size_t)i * NEXP);
            float4 w1 = *reinterpret_cast<const float4*>(gw2 + (size_t)i * NEXP + 4);
            acc[0] = fmaf(h, w0.x, acc[0]); acc[1] = fmaf(h, w0.y, acc[1]);
            acc[2] = fmaf(h, w0.z, acc[2]); acc[3] = fmaf(h, w0.w, acc[3]);
            acc[4] = fmaf(h, w1.x, acc[4]); acc[5] = fmaf(h, w1.y, acc[5]);
            acc[6] = fmaf(h, w1.z, acc[6]); acc[7] = fmaf(h, w1.w, acc[7]);
        }
        const int lane = threadIdx.x & 31, wd = threadIdx.x >> 5;
#pragma unroll
        for (int j = 0; j < NEXP; j++)
#pragma unroll
            for (int o = 16; o > 0; o >>= 1)
                acc[j] += __shfl_down_sync(0xffffffffu, acc[j], o);
        if (lane == 0) {
#pragma unroll
            for (int j = 0; j < NEXP; j++) red[wd][j] = acc[j];
        }
        __syncthreads();
        if (threadIdx.x == 0) {
            float l[NEXP];
#pragma unroll
            for (int j = 0; j < NEXP; j++) {
                l[j] = gb2[j];
#pragma unroll
                for (int w = 0; w < 8; w++) l[j] += red[w][j];
            }
            float mx = l[0];
#pragma unroll
            for (int j = 1; j < NEXP; j++) mx = fmaxf(mx, l[j]);
            float p[NEXP], s = 0.f;
#pragma unroll
            for (int j = 0; j < NEXP; j++) { p[j] = expf(l[j] - mx); s += p[j]; }
            float inv = 1.0f / s;
#pragma unroll
            for (int j = 0; j < NEXP; j++) p[j] *= inv;
            int i0 = 0;
#pragma unroll
            for (int j = 1; j < NEXP; j++) if (p[j] > p[i0]) i0 = j;
            int i1 = (i0 == 0) ? 1 : 0;
#pragma unroll
            for (int j = 0; j < NEXP; j++) if (j != i0 && p[j] > p[i1]) i1 = j;
            g_topk_idx[t * 2 + 0] = i0;  g_topk_w[t * 2 + 0] = p[i0];
            g_topk_idx[t * 2 + 1] = i1;  g_topk_w[t * 2 + 1] = p[i1];
        }
        __syncthreads();
    }
}

// ---------------- deterministic dispatch ----------------
__global__ void dispatch_count() {
    __shared__ int scnt[NEXP];
    if (threadIdx.x < NEXP) scnt[threadIdx.x] = 0;
    __syncthreads();
    int item = blockIdx.x * 256 + threadIdx.x;
    atomicAdd(&scnt[g_topk_idx[item]], 1);
    __syncthreads();
    if (threadIdx.x < NEXP) g_blockCnt[blockIdx.x * NEXP + threadIdx.x] = scnt[threadIdx.x];
}
// MLP-prefetch scan (R13 verified)
__global__ void dispatch_scan() {
    int e = threadIdx.x;
    if (e < NEXP) {
        int v[NBLK_DISP];
#pragma unroll
        for (int b = 0; b < NBLK_DISP; b++)
            v[b] = g_blockCnt[b * NEXP + e];
        int off = 0;
#pragma unroll
        for (int b = 0; b < NBLK_DISP; b++) {
            g_blockOff[b * NEXP + e] = off;
            off += v[b];
        }
        g_cnt[e] = off;
    }
    __syncthreads();
    if (threadIdx.x == 0) {
        int base = 0, mb = 0;
        for (int i = 0; i < NEXP; i++) {
            g_base[i] = base; base += g_cnt[i];
            g_mblkBase[i] = mb; mb += (g_cnt[i] + 127) >> 7;
        }
        g_mblkBase[NEXP] = mb;
    }
}
__global__ void dispatch_write() {
    __shared__ int se[256];
    const int i = threadIdx.x;
    const int item = blockIdx.x * 256 + i;
    const int e = g_topk_idx[item];
    se[i] = e;
    __syncthreads();
    int rank = 0;
    for (int j = 0; j < i; j++) rank += (se[j] == e);
    int pos = g_base[e] + g_blockOff[blockIdx.x * NEXP + e] + rank;
    g_list[pos]  = item >> 1;
    g_wlist[pos] = g_topk_w[item];
    g_slot[item] = pos;
}

// ---------------- launch ----------------
extern "C" void kernel_launch(void* const* d_in, const int* in_sizes, int n_in,
                              void* d_out, int out_size)
{
    const float* x   = (const float*)d_in[0];
    const float* gw1 = (const float*)d_in[2];
    const float* gb1 = (const float*)d_in[3];
    const float* gw2 = (const float*)d_in[4];
    const float* gb2 = (const float*)d_in[5];
    const float* We1 = (const float*)d_in[6];
    const float* be1 = (const float*)d_in[7];
    const float* We2 = (const float*)d_in[8];
    const float* be2 = (const float*)d_in[9];
    const float* Ws1 = (const float*)d_in[10];
    const float* bs1 = (const float*)d_in[11];
    const float* Ws2 = (const float*)d_in[12];
    const float* bs2 = (const float*)d_in[13];
    float* out = (float*)d_out;

    float  *h1;
    __half *hs, *he, *ho, *xhi, *Bg1h, *Bs1h, *Bs2h, *Be1h, *Be2h;
    cudaGetSymbolAddress((void**)&h1,   g_h1);
    cudaGetSymbolAddress((void**)&hs,   g_hs);
    cudaGetSymbolAddress((void**)&he,   g_he);
    cudaGetSymbolAddress((void**)&ho,   g_ho);
    cudaGetSymbolAddress((void**)&xhi,  g_xhi);
    cudaGetSymbolAddress((void**)&Bg1h, g_Bg1h);
    cudaGetSymbolAddress((void**)&Bs1h, g_Bs1h);
    cudaGetSymbolAddress((void**)&Bs2h, g_Bs2h);
    cudaGetSymbolAddress((void**)&Be1h, g_Be1h);
    cudaGetSymbolAddress((void**)&Be2h, g_Be2h);

    cudaFuncSetAttribute(gemm_f16<0,1,0>, cudaFuncAttributeMaxDynamicSharedMemorySize, SME_BYTES);
    cudaFuncSetAttribute(gemm_f16<0,2,1>, cudaFuncAttributeMaxDynamicSharedMemorySize, SME_BYTES);
    cudaFuncSetAttribute(gemm_f16<0,0,4>, cudaFuncAttributeMaxDynamicSharedMemorySize, SME_BYTES);
    cudaFuncSetAttribute(gemm_f16<1,2,1>, cudaFuncAttributeMaxDynamicSharedMemorySize, SME_BYTES);
    cudaFuncSetAttribute(gemm_f16<2,0,3>, cudaFuncAttributeMaxDynamicSharedMemorySize, SME_BYTES);

    // ---- prep: streaming fp32->fp16 converts (no transposes) ----
    cvt_hi<<<(T_TOK * DIMD / 8 + 255) / 256, 256>>>(x, xhi, T_TOK * DIMD / 8);
    cvt_w<<<(DIMD * DIMH / 8 + 255) / 256, 256>>>(gw1, Bg1h, DIMD * DIMH / 8);
    // gate hidden single-pass fp16, fp32 out
    gemm_f16<0,1,0><<<dim3(T_TOK / 128, DIMH / 128), 256, SME_BYTES>>>(xhi, Bg1h, gb1, h1, DIMD, DIMH);
    cvt_w<<<(DIMD * DIMH / 8 + 255) / 256, 256>>>(Ws1, Bs1h, DIMD * DIMH / 8);
    cvt_w<<<(DIMH * DIMD / 8 + 255) / 256, 256>>>(Ws2, Bs2h, DIMH * DIMD / 8);
    cvt_w<<<(NEXP * DIMD * DIMH / 8 + 255) / 256, 256>>>(We1, Be1h, NEXP * DIMD * DIMH / 8);
    cvt_w<<<(NEXP * DIMH * DIMD / 8 + 255) / 256, 256>>>(We2, Be2h, NEXP * DIMH * DIMD / 8);
    // routing + margin repair
    logits_topk<<<T_TOK, 256>>>(h1, gw2, gb2);
    sgemm_fix<<<dim3(T_TOK / 128, DIMH / 128), 256>>>(x, gw1, gb1, h1);
    repair_logits<<<512, 256>>>(h1, gw2, gb2);
    // dispatch
    dispatch_count<<<NBLK_DISP, 256>>>();
    dispatch_scan<<<1, 32>>>();
    dispatch_write<<<NBLK_DISP, 256>>>();
    // routed experts first (so shared2 can fuse the combine); ho fp16
    gemm_f16<1,2,1><<<dim3(136, DIMH / 128), 256, SME_BYTES>>>(xhi, Be1h, be1, he, DIMD, DIMH);
    gemm_f16<2,0,3><<<dim3(136, DIMD / 128), 256, SME_BYTES>>>(he,  Be2h, be2, ho, DIMH, DIMD);
    // shared expert; GEMM2 epilogue fuses routed combine
    gemm_f16<0,2,1><<<dim3(T_TOK / 128, DIMH / 128), 256, SME_BYTES>>>(xhi, Bs1h, bs1, hs,  DIMD, DIMH);
    gemm_f16<0,0,4><<<dim3(T_TOK / 128, DIMD / 128), 256, SME_BYTES>>>(hs,  Bs2h, bs2, out, DIMH, DIMD);
}

// round 15
// speedup vs baseline: 1.0794x; 1.0794x over previous
#include <cuda_runtime.h>
#include <cuda_fp16.h>
#include <cstdint>
#include <math.h>

// ---------------- problem constants ----------------
#define T_TOK 8192
#define DIMD  1024
#define DIMH  2048
#define NEXP  8
#define NITEM (T_TOK*2)
#define NBLK_DISP 64
#define MARGIN_TAU 1e-3f
#define TPB_LOG 4                     // tokens per logits block

// ---------------- scratch (device globals) ----------------
__device__ float  g_h1[(size_t)T_TOK * DIMH];           // gate hidden fp32; reused as repair buffer
__device__ __half g_hs[(size_t)T_TOK * DIMH];           // shared-expert hidden fp16
__device__ __half g_he[(size_t)NITEM * DIMH];           // routed hidden fp16 (compact)
__device__ __half g_ho[(size_t)NITEM * DIMD];           // routed out rows fp16 (weighted, compact)
__device__ __half g_xhi[(size_t)T_TOK * DIMD];
__device__ __half g_Bg1h[(size_t)DIMD * DIMH];          // gw1 fp16 (row-major [K,N])
__device__ __half g_Bs1h[(size_t)DIMD * DIMH];          // Ws1 fp16
__device__ __half g_Bs2h[(size_t)DIMH * DIMD];          // Ws2 fp16
__device__ __half g_Be1h[(size_t)NEXP * DIMD * DIMH];   // We1 fp16
__device__ __half g_Be2h[(size_t)NEXP * DIMH * DIMD];   // We2 fp16
__device__ int    g_topk_idx[NITEM];
__device__ float  g_topk_w[NITEM];
__device__ int    g_list[NITEM];
__device__ float  g_wlist[NITEM];
__device__ int    g_slot[NITEM];                        // item -> compact slot
__device__ int    g_cnt[NEXP];
__device__ int    g_base[NEXP];
__device__ int    g_mblkBase[NEXP + 1];
__device__ int    g_blockCnt[NBLK_DISP * NEXP];
__device__ int    g_blockOff[NBLK_DISP * NEXP];
__device__ int    g_fixCnt;
__device__ int    g_fixList[T_TOK];

// ---------------- small helpers (defined BEFORE use) ----------------
__device__ __forceinline__ uint32_t h2_as_u32(__half2 h) {
    return *reinterpret_cast<uint32_t*>(&h);
}
__device__ __forceinline__ uint32_t smem_u32(const void* p) {
    uint32_t a;
    asm("{ .reg .u64 t; cvta.to.shared.u64 t, %1; cvt.u32.u64 %0, t; }" : "=r"(a) : "l"(p));
    return a;
}
__device__ __forceinline__ void ldsm4(uint32_t& r0, uint32_t& r1, uint32_t& r2, uint32_t& r3, uint32_t a) {
    asm volatile("ldmatrix.sync.aligned.m8n8.x4.shared.b16 {%0,%1,%2,%3}, [%4];"
                 : "=r"(r0), "=r"(r1), "=r"(r2), "=r"(r3) : "r"(a));
}
__device__ __forceinline__ void ldsm4t(uint32_t& r0, uint32_t& r1, uint32_t& r2, uint32_t& r3, uint32_t a) {
    asm volatile("ldmatrix.sync.aligned.m8n8.x4.trans.shared.b16 {%0,%1,%2,%3}, [%4];"
                 : "=r"(r0), "=r"(r1), "=r"(r2), "=r"(r3) : "r"(a));
}
__device__ __forceinline__ void mma16816(float* d, const uint32_t* a, const uint32_t* b) {
    asm volatile("mma.sync.aligned.m16n8k16.row.col.f32.f16.f16.f32 "
                 "{%0,%1,%2,%3},{%4,%5,%6,%7},{%8,%9},{%0,%1,%2,%3};"
                 : "+f"(d[0]), "+f"(d[1]), "+f"(d[2]), "+f"(d[3])
                 : "r"(a[0]), "r"(a[1]), "r"(a[2]), "r"(a[3]), "r"(b[0]), "r"(b[1]));
}
#define CP_ASYNC16(sa, ga) asm volatile("cp.async.cg.shared.global [%0], [%1], 16;" :: "r"(sa), "l"(ga))
#define CP_COMMIT()        asm volatile("cp.async.commit_group;" ::: "memory")
template<int N> __device__ __forceinline__ void cp_wait() {
    asm volatile("cp.async.wait_group %0;" :: "n"(N) : "memory");
}

// ---------------- activations ----------------
__device__ __forceinline__ float gelu_erf(float v) {
    return 0.5f * v * (1.0f + erff(v * 0.70710678118654752f));
}
__device__ __forceinline__ float gelu_tanh(float v) {
    float u = 0.7978845608028654f * (v + 0.044715f * v * v * v);
    float t = __expf(2.0f * u);
    float th = 1.0f - __fdividef(2.0f, t + 1.0f);
    return 0.5f * v * (1.0f + th);
}

// ---------------- conversions (pure streaming, no transpose) ----------------
__global__ void cvt_hi(const float* __restrict__ src, __half* __restrict__ hi, int n8) {
    int i = blockIdx.x * blockDim.x + threadIdx.x;
    if (i == 0) g_fixCnt = 0;                           // fused reset
    if (i >= n8) return;
    float4 v0 = reinterpret_cast<const float4*>(src)[2 * i];
    float4 v1 = reinterpret_cast<const float4*>(src)[2 * i + 1];
    uint4 o;
    o.x = h2_as_u32(__halves2half2(__float2half_rn(v0.x), __float2half_rn(v0.y)));
    o.y = h2_as_u32(__halves2half2(__float2half_rn(v0.z), __float2half_rn(v0.w)));
    o.z = h2_as_u32(__halves2half2(__float2half_rn(v1.x), __float2half_rn(v1.y)));
    o.w = h2_as_u32(__halves2half2(__float2half_rn(v1.z), __float2half_rn(v1.w)));
    reinterpret_cast<uint4*>(hi)[i] = o;
}

__global__ void cvt_w(const float* __restrict__ src, __half* __restrict__ dst, int n8) {
    int i = blockIdx.x * blockDim.x + threadIdx.x;
    if (i >= n8) return;
    float4 v0 = reinterpret_cast<const float4*>(src)[2 * i];
    float4 v1 = reinterpret_cast<const float4*>(src)[2 * i + 1];
    uint4 o;
    o.x = h2_as_u32(__halves2half2(__float2half_rn(v0.x), __float2half_rn(v0.y)));
    o.y = h2_as_u32(__halves2half2(__float2half_rn(v0.z), __float2half_rn(v0.w)));
    o.z = h2_as_u32(__halves2half2(__float2half_rn(v1.x), __float2half_rn(v1.y)));
    o.w = h2_as_u32(__halves2half2(__float2half_rn(v1.z), __float2half_rn(v1.w)));
    reinterpret_cast<uint4*>(dst)[i] = o;
}

// ---------------- fp16 tensor GEMM: CTA 128x128, BK=64, 3-stage cp.async (R7 config) ----------------
// A row-major [M,K] (ldsm non-trans); B row-major [K,N] (ldsm.trans)
// MODE 0: dense A rows; 1: gather A rows via g_list (expert blocks); 2: dense compact A
// ACT 0: none, 1: gelu_erf, 2: gelu_tanh
// OUT 0: fp32 store; 1: fp16 store; 3: weighted fp16 store to compact row (base+m);
//     4: fp32 store + fused routed combine (out = v + ho[slot0] + ho[slot1], ho fp16)
#define ROWPAD_A 144
#define ROWPAD_B 272
#define TILE_A (128 * ROWPAD_A)       // 18432 B
#define TILE_B (64 * ROWPAD_B)        // 17408 B
#define STAGE_E (TILE_A + TILE_B)     // 35840 B
#define SME_BYTES (3 * STAGE_E)       // 107520 B

template<int MODE, int ACT, int OUT>
__global__ __launch_bounds__(256, 2)
void gemm_f16(const __half* __restrict__ A, const __half* __restrict__ B,
              const float* __restrict__ bias, void* __restrict__ Cv,
              int K, int ldn)
{
    int e = 0, m0, base = 0, cnt = 0;
    if (MODE == 0) {
        m0 = blockIdx.x * 128;
    } else {
        if ((int)blockIdx.x >= g_mblkBase[NEXP]) return;
#pragma unroll
        for (int i = 1; i < NEXP; i++) if ((int)blockIdx.x >= g_mblkBase[i]) e = i;
        m0 = ((int)blockIdx.x - g_mblkBase[e]) * 128;
        base = g_base[e]; cnt = g_cnt[e];
        B    += (size_t)e * K * ldn;
        bias += (size_t)e * ldn;
    }
    const int n0 = blockIdx.y * 128;

    extern __shared__ char smem[];
    const uint32_t sbase = smem_u32(smem);
    const int tid = threadIdx.x, lane = tid & 31, wid = tid >> 5;

    const int larow = tid >> 3;
    const uint32_t dstA = (uint32_t)(larow * ROWPAD_A + (tid & 7) * 16);
    const __half* aptr[4];
#pragma unroll
    for (int i = 0; i < 4; i++) {
        int m = m0 + larow + 32 * i;
        if (MODE == 0)      aptr[i] = A + (size_t)m * K;
        else if (MODE == 1) { int mm = (m < cnt) ? m : 0; aptr[i] = A + (size_t)g_list[base + mm] * K; }
        else                { int mm = (m < cnt) ? m : 0; aptr[i] = A + (size_t)(base + mm) * K; }
        aptr[i] += (tid & 7) * 8;
    }
    const int lbrow = tid >> 4;
    const uint32_t dstB = (uint32_t)(lbrow * ROWPAD_B + (tid & 15) * 16);
    const __half* bptr[4];
#pragma unroll
    for (int i = 0; i < 4; i++)
        bptr[i] = B + (size_t)(lbrow + 16 * i) * ldn + n0 + (tid & 15) * 8;

    const int S = K >> 6;
    auto issue = [&](int s) {
        uint32_t st = sbase + (uint32_t)((s % 3) * STAGE_E);
#pragma unroll
        for (int i = 0; i < 4; i++)
            CP_ASYNC16(st + dstA + (uint32_t)(32 * i * ROWPAD_A), (const void*)(aptr[i] + s * 64));
#pragma unroll
        for (int i = 0; i < 4; i++)
            CP_ASYNC16(st + TILE_A + dstB + (uint32_t)(16 * i * ROWPAD_B), (const void*)(bptr[i] + (size_t)s * 64 * ldn));
        CP_COMMIT();
    };
    issue(0);
    if (S > 1) issue(1);

    const int wm0 = (wid >> 1) * 32;
    const int wn0 = (wid & 1) * 64;
    const int arow_l = (lane & 7) + ((lane >> 3) & 1) * 8;
    const int acol_l = (lane >> 4) * 8;
    const int bkrow_l = (lane & 7) + ((lane >> 3) & 1) * 8;
    const int bncol_l = (lane >> 4) * 8;

    float acc[2][8][4];
#pragma unroll
    for (int i = 0; i < 2; i++)
#pragma unroll
        for (int j = 0; j < 8; j++)
#pragma unroll
            for (int q = 0; q < 4; q++) acc[i][j][q] = 0.f;

    for (int s = 0; s < S; s++) {
        if (s + 1 < S) cp_wait<1>(); else cp_wait<0>();
        __syncthreads();
        if (s + 2 < S) issue(s + 2);

        const uint32_t st = sbase + (uint32_t)((s % 3) * STAGE_E);
        const uint32_t sA = st, sB = st + TILE_A;
#pragma unroll
        for (int ks = 0; ks < 4; ks++) {
            const int k0 = ks * 16;
            uint32_t a[2][4], b[4][4];
#pragma unroll
            for (int mf = 0; mf < 2; mf++)
                ldsm4(a[mf][0], a[mf][1], a[mf][2], a[mf][3],
                      sA + (uint32_t)((wm0 + mf * 16 + arow_l) * ROWPAD_A + (k0 + acol_l) * 2));
#pragma unroll
            for (int p = 0; p < 4; p++)
                ldsm4t(b[p][0], b[p][1], b[p][2], b[p][3],
                       sB + (uint32_t)((k0 + bkrow_l) * ROWPAD_B + (wn0 + p * 16 + bncol_l) * 2));
#pragma unroll
            for (int mf = 0; mf < 2; mf++)
#pragma unroll
                for (int nf = 0; nf < 8; nf++)
                    mma16816(acc[mf][nf], a[mf], &b[nf >> 1][(nf & 1) * 2]);
        }
    }

    // ---- epilogue ----
    const int tr = lane >> 2, tc = (lane & 3) * 2;
#pragma unroll
    for (int mf = 0; mf < 2; mf++) {
#pragma unroll
        for (int half_ = 0; half_ < 2; half_++) {
            const int m = m0 + wm0 + mf * 16 + tr + half_ * 8;
            bool ok = (MODE == 0) || (m < cnt);
            if (!ok) continue;
            int orow = m; float wgt = 1.f;
            int s0 = 0, s1 = 0;
            if (MODE == 1) orow = base + m;
            if (MODE == 2) {
                if (OUT == 3) { orow = base + m; wgt = g_wlist[base + m]; }
                else          { orow = g_list[base + m]; wgt = g_wlist[base + m]; }
            }
            if (OUT == 4) { s0 = g_slot[2 * m]; s1 = g_slot[2 * m + 1]; }
#pragma unroll
            for (int nf = 0; nf < 8; nf++) {
                const int c = n0 + wn0 + nf * 8 + tc;
                float v0 = acc[mf][nf][half_ * 2 + 0] + bias[c];
                float v1 = acc[mf][nf][half_ * 2 + 1] + bias[c + 1];
                if (ACT == 1) { v0 = gelu_erf(v0);  v1 = gelu_erf(v1); }
                if (ACT == 2) { v0 = gelu_tanh(v0); v1 = gelu_tanh(v1); }
                if (OUT == 0) {
                    float2 w2; w2.x = v0; w2.y = v1;
                    *reinterpret_cast<float2*>((float*)Cv + (size_t)orow * ldn + c) = w2;
                } else if (OUT == 1) {
                    *reinterpret_cast<__half2*>((__half*)Cv + (size_t)orow * ldn + c) =
                        __halves2half2(__float2half_rn(v0), __float2half_rn(v1));
                } else if (OUT == 3) {
                    *reinterpret_cast<__half2*>((__half*)Cv + (size_t)orow * ldn + c) =
                        __halves2half2(__float2half_rn(wgt * v0), __float2half_rn(wgt * v1));
                } else { // OUT == 4: fused routed combine (ho fp16)
                    float2 r0 = __half22float2(*reinterpret_cast<const __half2*>(g_ho + (size_t)s0 * DIMD + c));
                    float2 r1 = __half22float2(*reinterpret_cast<const __half2*>(g_ho + (size_t)s1 * DIMD + c));
                    float2 w2; w2.x = v0 + r0.x + r1.x; w2.y = v1 + r0.y + r1.y;
                    *reinterpret_cast<float2*>((float*)Cv + (size_t)orow * ldn + c) = w2;
                }
            }
        }
    }
}

// ---------------- fp32 repair SGEMM: gathered rows (g_fixList), gelu_erf, compact out ----------------
__global__ __launch_bounds__(256, 2)
void sgemm_fix(const float* __restrict__ A, const float* __restrict__ B,
               const float* __restrict__ bias, float* __restrict__ C)
{
    const int cnt = g_fixCnt;
    const int m0 = blockIdx.x * 128;
    if (m0 >= cnt) return;
    const int n0 = blockIdx.y * 128;
    const int K = DIMD, N = DIMH;

    __shared__ float As[8][128];
    __shared__ float Bs[8][128];
    const int tid = threadIdx.x;
    const int aRow = tid >> 1, aCol = (tid & 1) * 4;
    const int bRow = tid >> 5, bCol = (tid & 31) * 4;

    int mA = m0 + aRow;
    int mm = (mA < cnt) ? mA : 0;
    const float* Arow = A + (size_t)g_fixList[mm] * K;
    const float* Bp = B + (size_t)bRow * N + n0 + bCol;

    const int ty = tid >> 4, tx = tid & 15;
    float acc[8][8];
#pragma unroll
    for (int i = 0; i < 8; i++)
#pragma unroll
        for (int j = 0; j < 8; j++) acc[i][j] = 0.f;

    for (int k0 = 0; k0 < K; k0 += 8) {
        float4 av = *reinterpret_cast<const float4*>(Arow + k0 + aCol);
        As[aCol + 0][aRow] = av.x; As[aCol + 1][aRow] = av.y;
        As[aCol + 2][aRow] = av.z; As[aCol + 3][aRow] = av.w;
        *reinterpret_cast<float4*>(&Bs[bRow][bCol]) = *reinterpret_cast<const float4*>(Bp + (size_t)k0 * N);
        __syncthreads();
#pragma unroll
        for (int kk = 0; kk < 8; kk++) {
            float4 a0 = *reinterpret_cast<const float4*>(&As[kk][ty * 8]);
            float4 a1 = *reinterpret_cast<const float4*>(&As[kk][ty * 8 + 4]);
            float4 b0 = *reinterpret_cast<const float4*>(&Bs[kk][tx * 8]);
            float4 b1 = *reinterpret_cast<const float4*>(&Bs[kk][tx * 8 + 4]);
            float a[8] = {a0.x, a0.y, a0.z, a0.w, a1.x, a1.y, a1.z, a1.w};
            float b[8] = {b0.x, b0.y, b0.z, b0.w, b1.x, b1.y, b1.z, b1.w};
#pragma unroll
            for (int i = 0; i < 8; i++)
#pragma unroll
                for (int j = 0; j < 8; j++)
                    acc[i][j] = fmaf(a[i], b[j], acc[i][j]);
        }
        __syncthreads();
    }
    const int cRow0 = m0 + ty * 8, cCol0 = n0 + tx * 8;
#pragma unroll
    for (int i = 0; i < 8; i++) {
        int m = cRow0 + i;
        if (m >= cnt) continue;
#pragma unroll
        for (int j = 0; j < 8; j++)
            C[(size_t)m * N + cCol0 + j] = gelu_erf(acc[i][j] + bias[cCol0 + j]);
    }
}

// ---------------- logits: 4 tokens/block (gw2 L2 traffic /4), R13 access pattern ----------------
__global__ void logits_topk(const float* __restrict__ h1,
                            const float* __restrict__ gw2,
                            const float* __restrict__ gb2)
{
    __shared__ float red[8][TPB_LOG][NEXP];
    const int t0 = blockIdx.x * TPB_LOG;
    float acc[TPB_LOG][NEXP];
#pragma unroll
    for (int tt = 0; tt < TPB_LOG; tt++)
#pragma unroll
        for (int j = 0; j < NEXP; j++) acc[tt][j] = 0.f;

    for (int i = threadIdx.x; i < DIMH; i += 256) {
        float4 w0 = *reinterpret_cast<const float4*>(gw2 + (size_t)i * NEXP);
        float4 w1 = *reinterpret_cast<const float4*>(gw2 + (size_t)i * NEXP + 4);
#pragma unroll
        for (int tt = 0; tt < TPB_LOG; tt++) {
            float h = h1[(size_t)(t0 + tt) * DIMH + i];
            acc[tt][0] = fmaf(h, w0.x, acc[tt][0]); acc[tt][1] = fmaf(h, w0.y, acc[tt][1]);
            acc[tt][2] = fmaf(h, w0.z, acc[tt][2]); acc[tt][3] = fmaf(h, w0.w, acc[tt][3]);
            acc[tt][4] = fmaf(h, w1.x, acc[tt][4]); acc[tt][5] = fmaf(h, w1.y, acc[tt][5]);
            acc[tt][6] = fmaf(h, w1.z, acc[tt][6]); acc[tt][7] = fmaf(h, w1.w, acc[tt][7]);
        }
    }
    const int lane = threadIdx.x & 31, wid = threadIdx.x >> 5;
#pragma unroll
    for (int tt = 0; tt < TPB_LOG; tt++)
#pragma unroll
        for (int j = 0; j < NEXP; j++)
#pragma unroll
            for (int o = 16; o > 0; o >>= 1)
                acc[tt][j] += __shfl_down_sync(0xffffffffu, acc[tt][j], o);
    if (lane == 0) {
#pragma unroll
        for (int tt = 0; tt < TPB_LOG; tt++)
#pragma unroll
            for (int j = 0; j < NEXP; j++) red[wid][tt][j] = acc[tt][j];
    }
    __syncthreads();
    if (threadIdx.x < TPB_LOG) {
        const int tt = threadIdx.x;
        const int t = t0 + tt;
        float l[NEXP];
#pragma unroll
        for (int j = 0; j < NEXP; j++) {
            l[j] = gb2[j];
#pragma unroll
            for (int w = 0; w < 8; w++) l[j] += red[w][tt][j];
        }
        float mx = l[0];
#pragma unroll
        for (int j = 1; j < NEXP; j++) mx = fmaxf(mx, l[j]);
        float p[NEXP], s = 0.f;
#pragma unroll
        for (int j = 0; j < NEXP; j++) { p[j] = expf(l[j] - mx); s += p[j]; }
        float inv = 1.0f / s;
#pragma unroll
        for (int j = 0; j < NEXP; j++) p[j] *= inv;
        int i0 = 0;
#pragma unroll
        for (int j = 1; j < NEXP; j++) if (p[j] > p[i0]) i0 = j;
        int i1 = (i0 == 0) ? 1 : 0;
#pragma unroll
        for (int j = 0; j < NEXP; j++) if (j != i0 && p[j] > p[i1]) i1 = j;
        g_topk_idx[t * 2 + 0] = i0;  g_topk_w[t * 2 + 0] = p[i0];
        g_topk_idx[t * 2 + 1] = i1;  g_topk_w[t * 2 + 1] = p[i1];
        float p2 = -1.f;
#pragma unroll
        for (int j = 0; j < NEXP; j++)
            if (j != i0 && j != i1 && p[j] > p2) p2 = p[j];
        if (p[i1] - p2 < MARGIN_TAU) {
            int ix = atomicAdd(&g_fixCnt, 1);
            g_fixList[ix] = t;
        }
    }
}

// ---------------- repair: exact fp32 logits for flagged tokens ----------------
__global__ void repair_logits(const float* __restrict__ hf,
                              const float* __restrict__ gw2,
                              const float* __restrict__ gb2)
{
    __shared__ float red[8][NEXP];
    for (int r = blockIdx.x; r < g_fixCnt; r += gridDim.x) {
        const int t = g_fixList[r];
        const float* hrow = hf + (size_t)r * DIMH;
        float acc[NEXP];
#pragma unroll
        for (int j = 0; j < NEXP; j++) acc[j] = 0.f;
        for (int i = threadIdx.x; i < DIMH; i += 256) {
            float h = hrow[i];
            float4 w0 = *reinterpret_cast<const float4*>(gw2 + (size_t)i * NEXP);
            float4 w1 = *reinterpret_cast<const float4*>(gw2 + (size_t)i * NEXP + 4);
            acc[0] = fmaf(h, w0.x, acc[0]); acc[1] = fmaf(h, w0.y, acc[1]);
            acc[2] = fmaf(h, w0.z, acc[2]); acc[3] = fmaf(h, w0.w, acc[3]);
            acc[4] = fmaf(h, w1.x, acc[4]); acc[5] = fmaf(h, w1.y, acc[5]);
            acc[6] = fmaf(h, w1.z, acc[6]); acc[7] = fmaf(h, w1.w, acc[7]);
        }
        const int lane = threadIdx.x & 31, wd = threadIdx.x >> 5;
#pragma unroll
        for (int j = 0; j < NEXP; j++)
#pragma unroll
            for (int o = 16; o > 0; o >>= 1)
                acc[j] += __shfl_down_sync(0xffffffffu, acc[j], o);
        if (lane == 0) {
#pragma unroll
            for (int j = 0; j < NEXP; j++) red[wd][j] = acc[j];
        }
        __syncthreads();
        if (threadIdx.x == 0) {
            float l[NEXP];
#pragma unroll
            for (int j = 0; j < NEXP; j++) {
                l[j] = gb2[j];
#pragma unroll
                for (int w = 0; w < 8; w++) l[j] += red[w][j];
            }
            float mx = l[0];
#pragma unroll
            for (int j = 1; j < NEXP; j++) mx = fmaxf(mx, l[j]);
            float p[NEXP], s = 0.f;
#pragma unroll
            for (int j = 0; j < NEXP; j++) { p[j] = expf(l[j] - mx); s += p[j]; }
            float inv = 1.0f / s;
#pragma unroll
            for (int j = 0; j < NEXP; j++) p[j] *= inv;
            int i0 = 0;
#pragma unroll
            for (int j = 1; j < NEXP; j++) if (p[j] > p[i0]) i0 = j;
            int i1 = (i0 == 0) ? 1 : 0;
#pragma unroll
            for (int j = 0; j < NEXP; j++) if (j != i0 && p[j] > p[i1]) i1 = j;
            g_topk_idx[t * 2 + 0] = i0;  g_topk_w[t * 2 + 0] = p[i0];
            g_topk_idx[t * 2 + 1] = i1;  g_topk_w[t * 2 + 1] = p[i1];
        }
        __syncthreads();
    }
}

// ---------------- deterministic dispatch ----------------
__global__ void dispatch_count() {
    __shared__ int scnt[NEXP];
    if (threadIdx.x < NEXP) scnt[threadIdx.x] = 0;
    __syncthreads();
    int item = blockIdx.x * 256 + threadIdx.x;
    atomicAdd(&scnt[g_topk_idx[item]], 1);
    __syncthreads();
    if (threadIdx.x < NEXP) g_blockCnt[blockIdx.x * NEXP + threadIdx.x] = scnt[threadIdx.x];
}
// MLP-prefetch scan (R13 verified)
__global__ void dispatch_scan() {
    int e = threadIdx.x;
    if (e < NEXP) {
        int v[NBLK_DISP];
#pragma unroll
        for (int b = 0; b < NBLK_DISP; b++)
            v[b] = g_blockCnt[b * NEXP + e];
        int off = 0;
#pragma unroll
        for (int b = 0; b < NBLK_DISP; b++) {
            g_blockOff[b * NEXP + e] = off;
            off += v[b];
        }
        g_cnt[e] = off;
    }
    __syncthreads();
    if (threadIdx.x == 0) {
        int base = 0, mb = 0;
        for (int i = 0; i < NEXP; i++) {
            g_base[i] = base; base += g_cnt[i];
            g_mblkBase[i] = mb; mb += (g_cnt[i] + 127) >> 7;
        }
        g_mblkBase[NEXP] = mb;
    }
}
__global__ void dispatch_write() {
    __shared__ int se[256];
    const int i = threadIdx.x;
    const int item = blockIdx.x * 256 + i;
    const int e = g_topk_idx[item];
    se[i] = e;
    __syncthreads();
    int rank = 0;
    for (int j = 0; j < i; j++) rank += (se[j] == e);
    int pos = g_base[e] + g_blockOff[blockIdx.x * NEXP + e] + rank;
    g_list[pos]  = item >> 1;
    g_wlist[pos] = g_topk_w[item];
    g_slot[item] = pos;
}

// ---------------- launch ----------------
extern "C" void kernel_launch(void* const* d_in, const int* in_sizes, int n_in,
                              void* d_out, int out_size)
{
    const float* x   = (const float*)d_in[0];
    const float* gw1 = (const float*)d_in[2];
    const float* gb1 = (const float*)d_in[3];
    const float* gw2 = (const float*)d_in[4];
    const float* gb2 = (const float*)d_in[5];
    const float* We1 = (const float*)d_in[6];
    const float* be1 = (const float*)d_in[7];
    const float* We2 = (const float*)d_in[8];
    const float* be2 = (const float*)d_in[9];
    const float* Ws1 = (const float*)d_in[10];
    const float* bs1 = (const float*)d_in[11];
    const float* Ws2 = (const float*)d_in[12];
    const float* bs2 = (const float*)d_in[13];
    float* out = (float*)d_out;

    float  *h1;
    __half *hs, *he, *ho, *xhi, *Bg1h, *Bs1h, *Bs2h, *Be1h, *Be2h;
    cudaGetSymbolAddress((void**)&h1,   g_h1);
    cudaGetSymbolAddress((void**)&hs,   g_hs);
    cudaGetSymbolAddress((void**)&he,   g_he);
    cudaGetSymbolAddress((void**)&ho,   g_ho);
    cudaGetSymbolAddress((void**)&xhi,  g_xhi);
    cudaGetSymbolAddress((void**)&Bg1h, g_Bg1h);
    cudaGetSymbolAddress((void**)&Bs1h, g_Bs1h);
    cudaGetSymbolAddress((void**)&Bs2h, g_Bs2h);
    cudaGetSymbolAddress((void**)&Be1h, g_Be1h);
    cudaGetSymbolAddress((void**)&Be2h, g_Be2h);

    cudaFuncSetAttribute(gemm_f16<0,1,0>, cudaFuncAttributeMaxDynamicSharedMemorySize, SME_BYTES);
    cudaFuncSetAttribute(gemm_f16<0,2,1>, cudaFuncAttributeMaxDynamicSharedMemorySize, SME_BYTES);
    cudaFuncSetAttribute(gemm_f16<0,0,4>, cudaFuncAttributeMaxDynamicSharedMemorySize, SME_BYTES);
    cudaFuncSetAttribute(gemm_f16<1,2,1>, cudaFuncAttributeMaxDynamicSharedMemorySize, SME_BYTES);
    cudaFuncSetAttribute(gemm_f16<2,0,3>, cudaFuncAttributeMaxDynamicSharedMemorySize, SME_BYTES);

    // ---- prep: streaming fp32->fp16 converts (no transposes) ----
    cvt_hi<<<(T_TOK * DIMD / 8 + 255) / 256, 256>>>(x, xhi, T_TOK * DIMD / 8);
    cvt_w<<<(DIMD * DIMH / 8 + 255) / 256, 256>>>(gw1, Bg1h, DIMD * DIMH / 8);
    // gate hidden single-pass fp16, fp32 out
    gemm_f16<0,1,0><<<dim3(T_TOK / 128, DIMH / 128), 256, SME_BYTES>>>(xhi, Bg1h, gb1, h1, DIMD, DIMH);
    cvt_w<<<(DIMD * DIMH / 8 + 255) / 256, 256>>>(Ws1, Bs1h, DIMD * DIMH / 8);
    cvt_w<<<(DIMH * DIMD / 8 + 255) / 256, 256>>>(Ws2, Bs2h, DIMH * DIMD / 8);
    cvt_w<<<(NEXP * DIMD * DIMH / 8 + 255) / 256, 256>>>(We1, Be1h, NEXP * DIMD * DIMH / 8);
    cvt_w<<<(NEXP * DIMH * DIMD / 8 + 255) / 256, 256>>>(We2, Be2h, NEXP * DIMH * DIMD / 8);
    // routing + margin repair
    logits_topk<<<T_TOK / TPB_LOG, 256>>>(h1, gw2, gb2);
    sgemm_fix<<<dim3(T_TOK / 128, DIMH / 128), 256>>>(x, gw1, gb1, h1);
    repair_logits<<<512, 256>>>(h1, gw2, gb2);
    // dispatch
    dispatch_count<<<NBLK_DISP, 256>>>();
    dispatch_scan<<<1, 32>>>();
    dispatch_write<<<NBLK_DISP, 256>>>();
    // routed experts first (so shared2 can fuse the combine); ho fp16
    gemm_f16<1,2,1><<<dim3(136, DIMH / 128), 256, SME_BYTES>>>(xhi, Be1h, be1, he, DIMD, DIMH);
    gemm_f16<2,0,3><<<dim3(136, DIMD / 128), 256, SME_BYTES>>>(he,  Be2h, be2, ho, DIMH, DIMD);
    // shared expert; GEMM2 epilogue fuses routed combine
    gemm_f16<0,2,1><<<dim3(T_TOK / 128, DIMH / 128), 256, SME_BYTES>>>(xhi, Bs1h, bs1, hs,  DIMD, DIMH);
    gemm_f16<0,0,4><<<dim3(T_TOK / 128, DIMD / 128), 256, SME_BYTES>>>(hs,  Bs2h, bs2, out, DIMH, DIMD);
}

// round 16
// speedup vs baseline: 1.0862x; 1.0063x over previous
#include <cuda_runtime.h>
#include <cuda_fp16.h>
#include <cstdint>
#include <math.h>

// ---------------- problem constants ----------------
#define T_TOK 8192
#define DIMD  1024
#define DIMH  2048
#define NEXP  8
#define NITEM (T_TOK*2)
#define NBLK_DISP 64
#define MARGIN_TAU 1e-3f
#define TPB_LOG 4                     // tokens per logits block

// ---------------- scratch (device globals) ----------------
__device__ float  g_h1[(size_t)T_TOK * DIMH];           // gate hidden fp32; reused as repair buffer
__device__ __half g_hs[(size_t)T_TOK * DIMH];           // shared-expert hidden fp16
__device__ __half g_he[(size_t)NITEM * DIMH];           // routed hidden fp16 (compact)
__device__ __half g_ho[(size_t)NITEM * DIMD];           // routed out rows fp16 (weighted, compact)
__device__ __half g_xhi[(size_t)T_TOK * DIMD];
__device__ __half g_Bg1h[(size_t)DIMD * DIMH];          // gw1 fp16 (row-major [K,N])
__device__ __half g_Bs1h[(size_t)DIMD * DIMH];          // Ws1 fp16
__device__ __half g_Bs2h[(size_t)DIMH * DIMD];          // Ws2 fp16
__device__ __half g_Be1h[(size_t)NEXP * DIMD * DIMH];   // We1 fp16
__device__ __half g_Be2h[(size_t)NEXP * DIMH * DIMD];   // We2 fp16
__device__ int    g_topk_idx[NITEM];
__device__ float  g_topk_w[NITEM];
__device__ int    g_list[NITEM];
__device__ float  g_wlist[NITEM];
__device__ int    g_slot[NITEM];                        // item -> compact slot
__device__ int    g_cnt[NEXP];
__device__ int    g_base[NEXP];
__device__ int    g_mblkBase[NEXP + 1];
__device__ int    g_blockCnt[NBLK_DISP * NEXP];
__device__ int    g_blockOff[NBLK_DISP * NEXP];
__device__ int    g_fixCnt;
__device__ int    g_fixList[T_TOK];

// ---------------- small helpers (defined BEFORE use) ----------------
__device__ __forceinline__ uint32_t h2_as_u32(__half2 h) {
    return *reinterpret_cast<uint32_t*>(&h);
}
__device__ __forceinline__ uint32_t smem_u32(const void* p) {
    uint32_t a;
    asm("{ .reg .u64 t; cvta.to.shared.u64 t, %1; cvt.u32.u64 %0, t; }" : "=r"(a) : "l"(p));
    return a;
}
__device__ __forceinline__ void ldsm4(uint32_t& r0, uint32_t& r1, uint32_t& r2, uint32_t& r3, uint32_t a) {
    asm volatile("ldmatrix.sync.aligned.m8n8.x4.shared.b16 {%0,%1,%2,%3}, [%4];"
                 : "=r"(r0), "=r"(r1), "=r"(r2), "=r"(r3) : "r"(a));
}
__device__ __forceinline__ void ldsm4t(uint32_t& r0, uint32_t& r1, uint32_t& r2, uint32_t& r3, uint32_t a) {
    asm volatile("ldmatrix.sync.aligned.m8n8.x4.trans.shared.b16 {%0,%1,%2,%3}, [%4];"
                 : "=r"(r0), "=r"(r1), "=r"(r2), "=r"(r3) : "r"(a));
}
__device__ __forceinline__ void mma16816(float* d, const uint32_t* a, const uint32_t* b) {
    asm volatile("mma.sync.aligned.m16n8k16.row.col.f32.f16.f16.f32 "
                 "{%0,%1,%2,%3},{%4,%5,%6,%7},{%8,%9},{%0,%1,%2,%3};"
                 : "+f"(d[0]), "+f"(d[1]), "+f"(d[2]), "+f"(d[3])
                 : "r"(a[0]), "r"(a[1]), "r"(a[2]), "r"(a[3]), "r"(b[0]), "r"(b[1]));
}
#define CP_ASYNC16(sa, ga) asm volatile("cp.async.cg.shared.global [%0], [%1], 16;" :: "r"(sa), "l"(ga))
#define CP_COMMIT()        asm volatile("cp.async.commit_group;" ::: "memory")
template<int N> __device__ __forceinline__ void cp_wait() {
    asm volatile("cp.async.wait_group %0;" :: "n"(N) : "memory");
}

// ---------------- activations ----------------
__device__ __forceinline__ float gelu_erf(float v) {
    return 0.5f * v * (1.0f + erff(v * 0.70710678118654752f));
}
__device__ __forceinline__ float gelu_tanh(float v) {
    float u = 0.7978845608028654f * (v + 0.044715f * v * v * v);
    float t = __expf(2.0f * u);
    float th = 1.0f - __fdividef(2.0f, t + 1.0f);
    return 0.5f * v * (1.0f + th);
}

// ---------------- conversions (pure streaming, no transpose) ----------------
__global__ void cvt_hi(const float* __restrict__ src, __half* __restrict__ hi, int n8) {
    int i = blockIdx.x * blockDim.x + threadIdx.x;
    if (i == 0) g_fixCnt = 0;                           // fused reset
    if (i >= n8) return;
    float4 v0 = reinterpret_cast<const float4*>(src)[2 * i];
    float4 v1 = reinterpret_cast<const float4*>(src)[2 * i + 1];
    uint4 o;
    o.x = h2_as_u32(__halves2half2(__float2half_rn(v0.x), __float2half_rn(v0.y)));
    o.y = h2_as_u32(__halves2half2(__float2half_rn(v0.z), __float2half_rn(v0.w)));
    o.z = h2_as_u32(__halves2half2(__float2half_rn(v1.x), __float2half_rn(v1.y)));
    o.w = h2_as_u32(__halves2half2(__float2half_rn(v1.z), __float2half_rn(v1.w)));
    reinterpret_cast<uint4*>(hi)[i] = o;
}

__global__ void cvt_w(const float* __restrict__ src, __half* __restrict__ dst, int n8) {
    int i = blockIdx.x * blockDim.x + threadIdx.x;
    if (i >= n8) return;
    float4 v0 = reinterpret_cast<const float4*>(src)[2 * i];
    float4 v1 = reinterpret_cast<const float4*>(src)[2 * i + 1];
    uint4 o;
    o.x = h2_as_u32(__halves2half2(__float2half_rn(v0.x), __float2half_rn(v0.y)));
    o.y = h2_as_u32(__halves2half2(__float2half_rn(v0.z), __float2half_rn(v0.w)));
    o.z = h2_as_u32(__halves2half2(__float2half_rn(v1.x), __float2half_rn(v1.y)));
    o.w = h2_as_u32(__halves2half2(__float2half_rn(v1.z), __float2half_rn(v1.w)));
    reinterpret_cast<uint4*>(dst)[i] = o;
}

// ---------------- fp16 tensor GEMM: CTA 128x128, BK=64, 3-stage cp.async (R7 config) ----------------
// A row-major [M,K] (ldsm non-trans); B row-major [K,N] (ldsm.trans)
// MODE 0: dense A rows; 1: gather A rows via g_list (expert blocks); 2: dense compact A
// ACT 0: none, 1: gelu_erf, 2: gelu_tanh
// OUT 0: fp32 store; 1: fp16 store; 3: weighted fp16 store to compact row (base+m);
//     4: fp32 store + fused routed combine (out = v + ho[slot0] + ho[slot1], ho fp16)
#define ROWPAD_A 144
#define ROWPAD_B 272
#define TILE_A (128 * ROWPAD_A)       // 18432 B
#define TILE_B (64 * ROWPAD_B)        // 17408 B
#define STAGE_E (TILE_A + TILE_B)     // 35840 B
#define SME_BYTES (3 * STAGE_E)       // 107520 B

template<int MODE, int ACT, int OUT>
__global__ __launch_bounds__(256, 2)
void gemm_f16(const __half* __restrict__ A, const __half* __restrict__ B,
              const float* __restrict__ bias, void* __restrict__ Cv,
              int K, int ldn)
{
    int e = 0, m0, base = 0, cnt = 0;
    if (MODE == 0) {
        m0 = blockIdx.x * 128;
    } else {
        if ((int)blockIdx.x >= g_mblkBase[NEXP]) return;
#pragma unroll
        for (int i = 1; i < NEXP; i++) if ((int)blockIdx.x >= g_mblkBase[i]) e = i;
        m0 = ((int)blockIdx.x - g_mblkBase[e]) * 128;
        base = g_base[e]; cnt = g_cnt[e];
        B    += (size_t)e * K * ldn;
        bias += (size_t)e * ldn;
    }
    const int n0 = blockIdx.y * 128;

    extern __shared__ char smem[];
    const uint32_t sbase = smem_u32(smem);
    const int tid = threadIdx.x, lane = tid & 31, wid = tid >> 5;

    const int larow = tid >> 3;
    const uint32_t dstA = (uint32_t)(larow * ROWPAD_A + (tid & 7) * 16);
    const __half* aptr[4];
#pragma unroll
    for (int i = 0; i < 4; i++) {
        int m = m0 + larow + 32 * i;
        if (MODE == 0)      aptr[i] = A + (size_t)m * K;
        else if (MODE == 1) { int mm = (m < cnt) ? m : 0; aptr[i] = A + (size_t)g_list[base + mm] * K; }
        else                { int mm = (m < cnt) ? m : 0; aptr[i] = A + (size_t)(base + mm) * K; }
        aptr[i] += (tid & 7) * 8;
    }
    const int lbrow = tid >> 4;
    const uint32_t dstB = (uint32_t)(lbrow * ROWPAD_B + (tid & 15) * 16);
    const __half* bptr[4];
#pragma unroll
    for (int i = 0; i < 4; i++)
        bptr[i] = B + (size_t)(lbrow + 16 * i) * ldn + n0 + (tid & 15) * 8;

    const int S = K >> 6;
    auto issue = [&](int s) {
        uint32_t st = sbase + (uint32_t)((s % 3) * STAGE_E);
#pragma unroll
        for (int i = 0; i < 4; i++)
            CP_ASYNC16(st + dstA + (uint32_t)(32 * i * ROWPAD_A), (const void*)(aptr[i] + s * 64));
#pragma unroll
        for (int i = 0; i < 4; i++)
            CP_ASYNC16(st + TILE_A + dstB + (uint32_t)(16 * i * ROWPAD_B), (const void*)(bptr[i] + (size_t)s * 64 * ldn));
        CP_COMMIT();
    };
    issue(0);
    if (S > 1) issue(1);

    const int wm0 = (wid >> 1) * 32;
    const int wn0 = (wid & 1) * 64;
    const int arow_l = (lane & 7) + ((lane >> 3) & 1) * 8;
    const int acol_l = (lane >> 4) * 8;
    const int bkrow_l = (lane & 7) + ((lane >> 3) & 1) * 8;
    const int bncol_l = (lane >> 4) * 8;

    float acc[2][8][4];
#pragma unroll
    for (int i = 0; i < 2; i++)
#pragma unroll
        for (int j = 0; j < 8; j++)
#pragma unroll
            for (int q = 0; q < 4; q++) acc[i][j][q] = 0.f;

    for (int s = 0; s < S; s++) {
        if (s + 1 < S) cp_wait<1>(); else cp_wait<0>();
        __syncthreads();
        if (s + 2 < S) issue(s + 2);

        const uint32_t st = sbase + (uint32_t)((s % 3) * STAGE_E);
        const uint32_t sA = st, sB = st + TILE_A;
#pragma unroll
        for (int ks = 0; ks < 4; ks++) {
            const int k0 = ks * 16;
            uint32_t a[2][4], b[4][4];
#pragma unroll
            for (int mf = 0; mf < 2; mf++)
                ldsm4(a[mf][0], a[mf][1], a[mf][2], a[mf][3],
                      sA + (uint32_t)((wm0 + mf * 16 + arow_l) * ROWPAD_A + (k0 + acol_l) * 2));
#pragma unroll
            for (int p = 0; p < 4; p++)
                ldsm4t(b[p][0], b[p][1], b[p][2], b[p][3],
                       sB + (uint32_t)((k0 + bkrow_l) * ROWPAD_B + (wn0 + p * 16 + bncol_l) * 2));
#pragma unroll
            for (int mf = 0; mf < 2; mf++)
#pragma unroll
                for (int nf = 0; nf < 8; nf++)
                    mma16816(acc[mf][nf], a[mf], &b[nf >> 1][(nf & 1) * 2]);
        }
    }

    // ---- epilogue ----
    const int tr = lane >> 2, tc = (lane & 3) * 2;
#pragma unroll
    for (int mf = 0; mf < 2; mf++) {
#pragma unroll
        for (int half_ = 0; half_ < 2; half_++) {
            const int m = m0 + wm0 + mf * 16 + tr + half_ * 8;
            bool ok = (MODE == 0) || (m < cnt);
            if (!ok) continue;
            int orow = m; float wgt = 1.f;
            int s0 = 0, s1 = 0;
            if (MODE == 1) orow = base + m;
            if (MODE == 2) {
                if (OUT == 3) { orow = base + m; wgt = g_wlist[base + m]; }
                else          { orow = g_list[base + m]; wgt = g_wlist[base + m]; }
            }
            if (OUT == 4) { s0 = g_slot[2 * m]; s1 = g_slot[2 * m + 1]; }
#pragma unroll
            for (int nf = 0; nf < 8; nf++) {
                const int c = n0 + wn0 + nf * 8 + tc;
                float v0 = acc[mf][nf][half_ * 2 + 0] + bias[c];
                float v1 = acc[mf][nf][half_ * 2 + 1] + bias[c + 1];
                if (ACT == 1) { v0 = gelu_erf(v0);  v1 = gelu_erf(v1); }
                if (ACT == 2) { v0 = gelu_tanh(v0); v1 = gelu_tanh(v1); }
                if (OUT == 0) {
                    float2 w2; w2.x = v0; w2.y = v1;
                    *reinterpret_cast<float2*>((float*)Cv + (size_t)orow * ldn + c) = w2;
                } else if (OUT == 1) {
                    *reinterpret_cast<__half2*>((__half*)Cv + (size_t)orow * ldn + c) =
                        __halves2half2(__float2half_rn(v0), __float2half_rn(v1));
                } else if (OUT == 3) {
                    *reinterpret_cast<__half2*>((__half*)Cv + (size_t)orow * ldn + c) =
                        __halves2half2(__float2half_rn(wgt * v0), __float2half_rn(wgt * v1));
                } else { // OUT == 4: fused routed combine (ho fp16)
                    float2 r0 = __half22float2(*reinterpret_cast<const __half2*>(g_ho + (size_t)s0 * DIMD + c));
                    float2 r1 = __half22float2(*reinterpret_cast<const __half2*>(g_ho + (size_t)s1 * DIMD + c));
                    float2 w2; w2.x = v0 + r0.x + r1.x; w2.y = v1 + r0.y + r1.y;
                    *reinterpret_cast<float2*>((float*)Cv + (size_t)orow * ldn + c) = w2;
                }
            }
        }
    }
}

// ---------------- fp32 repair SGEMM: gathered rows (g_fixList), gelu_erf, compact out ----------------
__global__ __launch_bounds__(256, 2)
void sgemm_fix(const float* __restrict__ A, const float* __restrict__ B,
               const float* __restrict__ bias, float* __restrict__ C)
{
    const int cnt = g_fixCnt;
    const int m0 = blockIdx.x * 128;
    if (m0 >= cnt) return;
    const int n0 = blockIdx.y * 128;
    const int K = DIMD, N = DIMH;

    __shared__ float As[8][128];
    __shared__ float Bs[8][128];
    const int tid = threadIdx.x;
    const int aRow = tid >> 1, aCol = (tid & 1) * 4;
    const int bRow = tid >> 5, bCol = (tid & 31) * 4;

    int mA = m0 + aRow;
    int mm = (mA < cnt) ? mA : 0;
    const float* Arow = A + (size_t)g_fixList[mm] * K;
    const float* Bp = B + (size_t)bRow * N + n0 + bCol;

    const int ty = tid >> 4, tx = tid & 15;
    float acc[8][8];
#pragma unroll
    for (int i = 0; i < 8; i++)
#pragma unroll
        for (int j = 0; j < 8; j++) acc[i][j] = 0.f;

    for (int k0 = 0; k0 < K; k0 += 8) {
        float4 av = *reinterpret_cast<const float4*>(Arow + k0 + aCol);
        As[aCol + 0][aRow] = av.x; As[aCol + 1][aRow] = av.y;
        As[aCol + 2][aRow] = av.z; As[aCol + 3][aRow] = av.w;
        *reinterpret_cast<float4*>(&Bs[bRow][bCol]) = *reinterpret_cast<const float4*>(Bp + (size_t)k0 * N);
        __syncthreads();
#pragma unroll
        for (int kk = 0; kk < 8; kk++) {
            float4 a0 = *reinterpret_cast<const float4*>(&As[kk][ty * 8]);
            float4 a1 = *reinterpret_cast<const float4*>(&As[kk][ty * 8 + 4]);
            float4 b0 = *reinterpret_cast<const float4*>(&Bs[kk][tx * 8]);
            float4 b1 = *reinterpret_cast<const float4*>(&Bs[kk][tx * 8 + 4]);
            float a[8] = {a0.x, a0.y, a0.z, a0.w, a1.x, a1.y, a1.z, a1.w};
            float b[8] = {b0.x, b0.y, b0.z, b0.w, b1.x, b1.y, b1.z, b1.w};
#pragma unroll
            for (int i = 0; i < 8; i++)
#pragma unroll
                for (int j = 0; j < 8; j++)
                    acc[i][j] = fmaf(a[i], b[j], acc[i][j]);
        }
        __syncthreads();
    }
    const int cRow0 = m0 + ty * 8, cCol0 = n0 + tx * 8;
#pragma unroll
    for (int i = 0; i < 8; i++) {
        int m = cRow0 + i;
        if (m >= cnt) continue;
#pragma unroll
        for (int j = 0; j < 8; j++)
            C[(size_t)m * N + cCol0 + j] = gelu_erf(acc[i][j] + bias[cCol0 + j]);
    }
}

// ---------------- logits: 4 tokens/block (R15 verified) ----------------
__global__ void logits_topk(const float* __restrict__ h1,
                            const float* __restrict__ gw2,
                            const float* __restrict__ gb2)
{
    __shared__ float red[8][TPB_LOG][NEXP];
    const int t0 = blockIdx.x * TPB_LOG;
    float acc[TPB_LOG][NEXP];
#pragma unroll
    for (int tt = 0; tt < TPB_LOG; tt++)
#pragma unroll
        for (int j = 0; j < NEXP; j++) acc[tt][j] = 0.f;

    for (int i = threadIdx.x; i < DIMH; i += 256) {
        float4 w0 = *reinterpret_cast<const float4*>(gw2 + (size_t)i * NEXP);
        float4 w1 = *reinterpret_cast<const float4*>(gw2 + (size_t)i * NEXP + 4);
#pragma unroll
        for (int tt = 0; tt < TPB_LOG; tt++) {
            float h = h1[(size_t)(t0 + tt) * DIMH + i];
            acc[tt][0] = fmaf(h, w0.x, acc[tt][0]); acc[tt][1] = fmaf(h, w0.y, acc[tt][1]);
            acc[tt][2] = fmaf(h, w0.z, acc[tt][2]); acc[tt][3] = fmaf(h, w0.w, acc[tt][3]);
            acc[tt][4] = fmaf(h, w1.x, acc[tt][4]); acc[tt][5] = fmaf(h, w1.y, acc[tt][5]);
            acc[tt][6] = fmaf(h, w1.z, acc[tt][6]); acc[tt][7] = fmaf(h, w1.w, acc[tt][7]);
        }
    }
    const int lane = threadIdx.x & 31, wid = threadIdx.x >> 5;
#pragma unroll
    for (int tt = 0; tt < TPB_LOG; tt++)
#pragma unroll
        for (int j = 0; j < NEXP; j++)
#pragma unroll
            for (int o = 16; o > 0; o >>= 1)
                acc[tt][j] += __shfl_down_sync(0xffffffffu, acc[tt][j], o);
    if (lane == 0) {
#pragma unroll
        for (int tt = 0; tt < TPB_LOG; tt++)
#pragma unroll
            for (int j = 0; j < NEXP; j++) red[wid][tt][j] = acc[tt][j];
    }
    __syncthreads();
    if (threadIdx.x < TPB_LOG) {
        const int tt = threadIdx.x;
        const int t = t0 + tt;
        float l[NEXP];
#pragma unroll
        for (int j = 0; j < NEXP; j++) {
            l[j] = gb2[j];
#pragma unroll
            for (int w = 0; w < 8; w++) l[j] += red[w][tt][j];
        }
        float mx = l[0];
#pragma unroll
        for (int j = 1; j < NEXP; j++) mx = fmaxf(mx, l[j]);
        float p[NEXP], s = 0.f;
#pragma unroll
        for (int j = 0; j < NEXP; j++) { p[j] = expf(l[j] - mx); s += p[j]; }
        float inv = 1.0f / s;
#pragma unroll
        for (int j = 0; j < NEXP; j++) p[j] *= inv;
        int i0 = 0;
#pragma unroll
        for (int j = 1; j < NEXP; j++) if (p[j] > p[i0]) i0 = j;
        int i1 = (i0 == 0) ? 1 : 0;
#pragma unroll
        for (int j = 0; j < NEXP; j++) if (j != i0 && p[j] > p[i1]) i1 = j;
        g_topk_idx[t * 2 + 0] = i0;  g_topk_w[t * 2 + 0] = p[i0];
        g_topk_idx[t * 2 + 1] = i1;  g_topk_w[t * 2 + 1] = p[i1];
        float p2 = -1.f;
#pragma unroll
        for (int j = 0; j < NEXP; j++)
            if (j != i0 && j != i1 && p[j] > p2) p2 = p[j];
        if (p[i1] - p2 < MARGIN_TAU) {
            int ix = atomicAdd(&g_fixCnt, 1);
            g_fixList[ix] = t;
        }
    }
}

// ---------------- repair: exact fp32 logits for flagged tokens ----------------
__global__ void repair_logits(const float* __restrict__ hf,
                              const float* __restrict__ gw2,
                              const float* __restrict__ gb2)
{
    __shared__ float red[8][NEXP];
    for (int r = blockIdx.x; r < g_fixCnt; r += gridDim.x) {
        const int t = g_fixList[r];
        const float* hrow = hf + (size_t)r * DIMH;
        float acc[NEXP];
#pragma unroll
        for (int j = 0; j < NEXP; j++) acc[j] = 0.f;
        for (int i = threadIdx.x; i < DIMH; i += 256) {
            float h = hrow[i];
            float4 w0 = *reinterpret_cast<const float4*>(gw2 + (size_t)i * NEXP);
            float4 w1 = *reinterpret_cast<const float4*>(gw2 + (size_t)i * NEXP + 4);
            acc[0] = fmaf(h, w0.x, acc[0]); acc[1] = fmaf(h, w0.y, acc[1]);
            acc[2] = fmaf(h, w0.z, acc[2]); acc[3] = fmaf(h, w0.w, acc[3]);
            acc[4] = fmaf(h, w1.x, acc[4]); acc[5] = fmaf(h, w1.y, acc[5]);
            acc[6] = fmaf(h, w1.z, acc[6]); acc[7] = fmaf(h, w1.w, acc[7]);
        }
        const int lane = threadIdx.x & 31, wd = threadIdx.x >> 5;
#pragma unroll
        for (int j = 0; j < NEXP; j++)
#pragma unroll
            for (int o = 16; o > 0; o >>= 1)
                acc[j] += __shfl_down_sync(0xffffffffu, acc[j], o);
        if (lane == 0) {
#pragma unroll
            for (int j = 0; j < NEXP; j++) red[wd][j] = acc[j];
        }
        __syncthreads();
        if (threadIdx.x == 0) {
            float l[NEXP];
#pragma unroll
            for (int j = 0; j < NEXP; j++) {
                l[j] = gb2[j];
#pragma unroll
                for (int w = 0; w < 8; w++) l[j] += red[w][j];
            }
            float mx = l[0];
#pragma unroll
            for (int j = 1; j < NEXP; j++) mx = fmaxf(mx, l[j]);
            float p[NEXP], s = 0.f;
#pragma unroll
            for (int j = 0; j < NEXP; j++) { p[j] = expf(l[j] - mx); s += p[j]; }
            float inv = 1.0f / s;
#pragma unroll
            for (int j = 0; j < NEXP; j++) p[j] *= inv;
            int i0 = 0;
#pragma unroll
            for (int j = 1; j < NEXP; j++) if (p[j] > p[i0]) i0 = j;
            int i1 = (i0 == 0) ? 1 : 0;
#pragma unroll
            for (int j = 0; j < NEXP; j++) if (j != i0 && p[j] > p[i1]) i1 = j;
            g_topk_idx[t * 2 + 0] = i0;  g_topk_w[t * 2 + 0] = p[i0];
            g_topk_idx[t * 2 + 1] = i1;  g_topk_w[t * 2 + 1] = p[i1];
        }
        __syncthreads();
    }
}

// ---------------- deterministic dispatch ----------------
__global__ void dispatch_count() {
    __shared__ int scnt[NEXP];
    if (threadIdx.x < NEXP) scnt[threadIdx.x] = 0;
    __syncthreads();
    int item = blockIdx.x * 256 + threadIdx.x;
    atomicAdd(&scnt[g_topk_idx[item]], 1);
    __syncthreads();
    if (threadIdx.x < NEXP) g_blockCnt[blockIdx.x * NEXP + threadIdx.x] = scnt[threadIdx.x];
}
// MLP-prefetch scan (R13 verified)
__global__ void dispatch_scan() {
    int e = threadIdx.x;
    if (e < NEXP) {
        int v[NBLK_DISP];
#pragma unroll
        for (int b = 0; b < NBLK_DISP; b++)
            v[b] = g_blockCnt[b * NEXP + e];
        int off = 0;
#pragma unroll
        for (int b = 0; b < NBLK_DISP; b++) {
            g_blockOff[b * NEXP + e] = off;
            off += v[b];
        }
        g_cnt[e] = off;
    }
    __syncthreads();
    if (threadIdx.x == 0) {
        int base = 0, mb = 0;
        for (int i = 0; i < NEXP; i++) {
            g_base[i] = base; base += g_cnt[i];
            g_mblkBase[i] = mb; mb += (g_cnt[i] + 127) >> 7;
        }
        g_mblkBase[NEXP] = mb;
    }
}
__global__ void dispatch_write() {
    __shared__ int se[256];
    const int i = threadIdx.x;
    const int item = blockIdx.x * 256 + i;
    const int e = g_topk_idx[item];
    se[i] = e;
    __syncthreads();
    int rank = 0;
    for (int j = 0; j < i; j++) rank += (se[j] == e);
    int pos = g_base[e] + g_blockOff[blockIdx.x * NEXP + e] + rank;
    g_list[pos]  = item >> 1;
    g_wlist[pos] = g_topk_w[item];
    g_slot[item] = pos;
}

// ---------------- launch ----------------
extern "C" void kernel_launch(void* const* d_in, const int* in_sizes, int n_in,
                              void* d_out, int out_size)
{
    const float* x   = (const float*)d_in[0];
    const float* gw1 = (const float*)d_in[2];
    const float* gb1 = (const float*)d_in[3];
    const float* gw2 = (const float*)d_in[4];
    const float* gb2 = (const float*)d_in[5];
    const float* We1 = (const float*)d_in[6];
    const float* be1 = (const float*)d_in[7];
    const float* We2 = (const float*)d_in[8];
    const float* be2 = (const float*)d_in[9];
    const float* Ws1 = (const float*)d_in[10];
    const float* bs1 = (const float*)d_in[11];
    const float* Ws2 = (const float*)d_in[12];
    const float* bs2 = (const float*)d_in[13];
    float* out = (float*)d_out;

    float  *h1;
    __half *hs, *he, *ho, *xhi, *Bg1h, *Bs1h, *Bs2h, *Be1h, *Be2h;
    cudaGetSymbolAddress((void**)&h1,   g_h1);
    cudaGetSymbolAddress((void**)&hs,   g_hs);
    cudaGetSymbolAddress((void**)&he,   g_he);
    cudaGetSymbolAddress((void**)&ho,   g_ho);
    cudaGetSymbolAddress((void**)&xhi,  g_xhi);
    cudaGetSymbolAddress((void**)&Bg1h, g_Bg1h);
    cudaGetSymbolAddress((void**)&Bs1h, g_Bs1h);
    cudaGetSymbolAddress((void**)&Bs2h, g_Bs2h);
    cudaGetSymbolAddress((void**)&Be1h, g_Be1h);
    cudaGetSymbolAddress((void**)&Be2h, g_Be2h);

    cudaFuncSetAttribute(gemm_f16<0,1,0>, cudaFuncAttributeMaxDynamicSharedMemorySize, SME_BYTES);
    cudaFuncSetAttribute(gemm_f16<0,2,1>, cudaFuncAttributeMaxDynamicSharedMemorySize, SME_BYTES);
    cudaFuncSetAttribute(gemm_f16<0,0,4>, cudaFuncAttributeMaxDynamicSharedMemorySize, SME_BYTES);
    cudaFuncSetAttribute(gemm_f16<1,2,1>, cudaFuncAttributeMaxDynamicSharedMemorySize, SME_BYTES);
    cudaFuncSetAttribute(gemm_f16<2,0,3>, cudaFuncAttributeMaxDynamicSharedMemorySize, SME_BYTES);

    // side stream + fork/join events (host objects; created once; no device memory)
    static cudaStream_t s2 = nullptr;
    static cudaEvent_t evFork = nullptr, evJoin = nullptr;
    if (s2 == nullptr) {
        cudaStreamCreateWithFlags(&s2, cudaStreamNonBlocking);
        cudaEventCreateWithFlags(&evFork, cudaEventDisableTiming);
        cudaEventCreateWithFlags(&evJoin, cudaEventDisableTiming);
    }

    // ---- main stream: x convert (also resets fixCnt) ----
    cvt_hi<<<(T_TOK * DIMD / 8 + 255) / 256, 256>>>(x, xhi, T_TOK * DIMD / 8);

    // ---- fork: big expert-weight converts run concurrently on s2 ----
    cudaEventRecord(evFork, 0);
    cudaStreamWaitEvent(s2, evFork, 0);
    cvt_w<<<(NEXP * DIMD * DIMH / 8 + 255) / 256, 256, 0, s2>>>(We1, Be1h, NEXP * DIMD * DIMH / 8);
    cvt_w<<<(NEXP * DIMH * DIMD / 8 + 255) / 256, 256, 0, s2>>>(We2, Be2h, NEXP * DIMH * DIMD / 8);
    cudaEventRecord(evJoin, s2);

    // ---- main stream: gate pipeline (independent of We converts) ----
    cvt_w<<<(DIMD * DIMH / 8 + 255) / 256, 256>>>(gw1, Bg1h, DIMD * DIMH / 8);
    gemm_f16<0,1,0><<<dim3(T_TOK / 128, DIMH / 128), 256, SME_BYTES>>>(xhi, Bg1h, gb1, h1, DIMD, DIMH);
    cvt_w<<<(DIMD * DIMH / 8 + 255) / 256, 256>>>(Ws1, Bs1h, DIMD * DIMH / 8);
    cvt_w<<<(DIMH * DIMD / 8 + 255) / 256, 256>>>(Ws2, Bs2h, DIMH * DIMD / 8);
    logits_topk<<<T_TOK / TPB_LOG, 256>>>(h1, gw2, gb2);
    sgemm_fix<<<dim3(T_TOK / 128, DIMH / 128), 256>>>(x, gw1, gb1, h1);
    repair_logits<<<512, 256>>>(h1, gw2, gb2);
    dispatch_count<<<NBLK_DISP, 256>>>();
    dispatch_scan<<<1, 32>>>();
    dispatch_write<<<NBLK_DISP, 256>>>();

    // ---- join: routed GEMMs need Be1h/Be2h ----
    cudaStreamWaitEvent(0, evJoin, 0);
    gemm_f16<1,2,1><<<dim3(136, DIMH / 128), 256, SME_BYTES>>>(xhi, Be1h, be1, he, DIMD, DIMH);
    gemm_f16<2,0,3><<<dim3(136, DIMD / 128), 256, SME_BYTES>>>(he,  Be2h, be2, ho, DIMH, DIMD);
    // shared expert; GEMM2 epilogue fuses routed combine
    gemm_f16<0,2,1><<<dim3(T_TOK / 128, DIMH / 128), 256, SME_BYTES>>>(xhi, Bs1h, bs1, hs,  DIMD, DIMH);
    gemm_f16<0,0,4><<<dim3(T_TOK / 128, DIMD / 128), 256, SME_BYTES>>>(hs,  Bs2h, bs2, out, DIMH, DIMD);
}

// round 17
// speedup vs baseline: 1.0901x; 1.0036x over previous
#include <cuda_runtime.h>
#include <cuda_fp16.h>
#include <cstdint>
#include <math.h>

// ---------------- problem constants ----------------
#define T_TOK 8192
#define DIMD  1024
#define DIMH  2048
#define NEXP  8
#define NITEM (T_TOK*2)
#define NBLK_DISP 64
#define MARGIN_TAU 1e-3f
#define TPB_LOG 4                     // tokens per logits block

// ---------------- scratch (device globals) ----------------
__device__ float  g_h1[(size_t)T_TOK * DIMH];           // gate hidden fp32; reused as repair buffer
__device__ __half g_hs[(size_t)T_TOK * DIMH];           // shared-expert hidden fp16
__device__ __half g_he[(size_t)NITEM * DIMH];           // routed hidden fp16 (compact)
__device__ __half g_ho[(size_t)NITEM * DIMD];           // routed out rows fp16 (weighted, compact)
__device__ __half g_xhi[(size_t)T_TOK * DIMD];
__device__ __half g_Bg1h[(size_t)DIMD * DIMH];          // gw1 fp16 (row-major [K,N])
__device__ __half g_Bs1h[(size_t)DIMD * DIMH];          // Ws1 fp16
__device__ __half g_Bs2h[(size_t)DIMH * DIMD];          // Ws2 fp16
__device__ __half g_Be1h[(size_t)NEXP * DIMD * DIMH];   // We1 fp16
__device__ __half g_Be2h[(size_t)NEXP * DIMH * DIMD];   // We2 fp16
__device__ int    g_topk_idx[NITEM];
__device__ float  g_topk_w[NITEM];
__device__ int    g_list[NITEM];
__device__ float  g_wlist[NITEM];
__device__ int    g_slot[NITEM];                        // item -> compact slot
__device__ int    g_cnt[NEXP];
__device__ int    g_base[NEXP];
__device__ int    g_mblkBase[NEXP + 1];
__device__ int    g_blockCnt[NBLK_DISP * NEXP];
__device__ int    g_blockOff[NBLK_DISP * NEXP];
__device__ int    g_fixCnt;
__device__ int    g_fixList[T_TOK];

// ---------------- small helpers (defined BEFORE use) ----------------
__device__ __forceinline__ uint32_t h2_as_u32(__half2 h) {
    return *reinterpret_cast<uint32_t*>(&h);
}
__device__ __forceinline__ uint32_t smem_u32(const void* p) {
    uint32_t a;
    asm("{ .reg .u64 t; cvta.to.shared.u64 t, %1; cvt.u32.u64 %0, t; }" : "=r"(a) : "l"(p));
    return a;
}
__device__ __forceinline__ void ldsm4(uint32_t& r0, uint32_t& r1, uint32_t& r2, uint32_t& r3, uint32_t a) {
    asm volatile("ldmatrix.sync.aligned.m8n8.x4.shared.b16 {%0,%1,%2,%3}, [%4];"
                 : "=r"(r0), "=r"(r1), "=r"(r2), "=r"(r3) : "r"(a));
}
__device__ __forceinline__ void ldsm4t(uint32_t& r0, uint32_t& r1, uint32_t& r2, uint32_t& r3, uint32_t a) {
    asm volatile("ldmatrix.sync.aligned.m8n8.x4.trans.shared.b16 {%0,%1,%2,%3}, [%4];"
                 : "=r"(r0), "=r"(r1), "=r"(r2), "=r"(r3) : "r"(a));
}
__device__ __forceinline__ void mma16816(float* d, const uint32_t* a, const uint32_t* b) {
    asm volatile("mma.sync.aligned.m16n8k16.row.col.f32.f16.f16.f32 "
                 "{%0,%1,%2,%3},{%4,%5,%6,%7},{%8,%9},{%0,%1,%2,%3};"
                 : "+f"(d[0]), "+f"(d[1]), "+f"(d[2]), "+f"(d[3])
                 : "r"(a[0]), "r"(a[1]), "r"(a[2]), "r"(a[3]), "r"(b[0]), "r"(b[1]));
}
#define CP_ASYNC16(sa, ga) asm volatile("cp.async.cg.shared.global [%0], [%1], 16;" :: "r"(sa), "l"(ga))
#define CP_COMMIT()        asm volatile("cp.async.commit_group;" ::: "memory")
template<int N> __device__ __forceinline__ void cp_wait() {
    asm volatile("cp.async.wait_group %0;" :: "n"(N) : "memory");
}

// ---------------- activations ----------------
__device__ __forceinline__ float gelu_erf(float v) {
    return 0.5f * v * (1.0f + erff(v * 0.70710678118654752f));
}
__device__ __forceinline__ float gelu_tanh(float v) {
    float u = 0.7978845608028654f * (v + 0.044715f * v * v * v);
    float t = __expf(2.0f * u);
    float th = 1.0f - __fdividef(2.0f, t + 1.0f);
    return 0.5f * v * (1.0f + th);
}

// ---------------- conversions (pure streaming, no transpose) ----------------
__global__ void cvt_hi(const float* __restrict__ src, __half* __restrict__ hi, int n8) {
    int i = blockIdx.x * blockDim.x + threadIdx.x;
    if (i == 0) g_fixCnt = 0;                           // fused reset
    if (i >= n8) return;
    float4 v0 = reinterpret_cast<const float4*>(src)[2 * i];
    float4 v1 = reinterpret_cast<const float4*>(src)[2 * i + 1];
    uint4 o;
    o.x = h2_as_u32(__halves2half2(__float2half_rn(v0.x), __float2half_rn(v0.y)));
    o.y = h2_as_u32(__halves2half2(__float2half_rn(v0.z), __float2half_rn(v0.w)));
    o.z = h2_as_u32(__halves2half2(__float2half_rn(v1.x), __float2half_rn(v1.y)));
    o.w = h2_as_u32(__halves2half2(__float2half_rn(v1.z), __float2half_rn(v1.w)));
    reinterpret_cast<uint4*>(hi)[i] = o;
}

__global__ void cvt_w(const float* __restrict__ src, __half* __restrict__ dst, int n8) {
    int i = blockIdx.x * blockDim.x + threadIdx.x;
    if (i >= n8) return;
    float4 v0 = reinterpret_cast<const float4*>(src)[2 * i];
    float4 v1 = reinterpret_cast<const float4*>(src)[2 * i + 1];
    uint4 o;
    o.x = h2_as_u32(__halves2half2(__float2half_rn(v0.x), __float2half_rn(v0.y)));
    o.y = h2_as_u32(__halves2half2(__float2half_rn(v0.z), __float2half_rn(v0.w)));
    o.z = h2_as_u32(__halves2half2(__float2half_rn(v1.x), __float2half_rn(v1.y)));
    o.w = h2_as_u32(__halves2half2(__float2half_rn(v1.z), __float2half_rn(v1.w)));
    reinterpret_cast<uint4*>(dst)[i] = o;
}

// ---------------- fp16 tensor GEMM: CTA 128x128, BK=64, 3-stage cp.async (R7 config) ----------------
// A row-major [M,K] (ldsm non-trans); B row-major [K,N] (ldsm.trans)
// MODE 0: dense A rows; 1: gather A rows via g_list (expert blocks); 2: dense compact A
// ACT 0: none, 1: gelu_erf, 2: gelu_tanh
// OUT 0: fp32 store; 1: fp16 store; 3: weighted fp16 store to compact row (base+m);
//     4: fp32 store + fused routed combine (out = v + ho[slot0] + ho[slot1], ho fp16)
#define ROWPAD_A 144
#define ROWPAD_B 272
#define TILE_A (128 * ROWPAD_A)       // 18432 B
#define TILE_B (64 * ROWPAD_B)        // 17408 B
#define STAGE_E (TILE_A + TILE_B)     // 35840 B
#define SME_BYTES (3 * STAGE_E)       // 107520 B

template<int MODE, int ACT, int OUT>
__global__ __launch_bounds__(256, 2)
void gemm_f16(const __half* __restrict__ A, const __half* __restrict__ B,
              const float* __restrict__ bias, void* __restrict__ Cv,
              int K, int ldn)
{
    int e = 0, m0, base = 0, cnt = 0;
    if (MODE == 0) {
        m0 = blockIdx.x * 128;
    } else {
        if ((int)blockIdx.x >= g_mblkBase[NEXP]) return;
#pragma unroll
        for (int i = 1; i < NEXP; i++) if ((int)blockIdx.x >= g_mblkBase[i]) e = i;
        m0 = ((int)blockIdx.x - g_mblkBase[e]) * 128;
        base = g_base[e]; cnt = g_cnt[e];
        B    += (size_t)e * K * ldn;
        bias += (size_t)e * ldn;
    }
    const int n0 = blockIdx.y * 128;

    extern __shared__ char smem[];
    const uint32_t sbase = smem_u32(smem);
    const int tid = threadIdx.x, lane = tid & 31, wid = tid >> 5;

    const int larow = tid >> 3;
    const uint32_t dstA = (uint32_t)(larow * ROWPAD_A + (tid & 7) * 16);
    const __half* aptr[4];
#pragma unroll
    for (int i = 0; i < 4; i++) {
        int m = m0 + larow + 32 * i;
        if (MODE == 0)      aptr[i] = A + (size_t)m * K;
        else if (MODE == 1) { int mm = (m < cnt) ? m : 0; aptr[i] = A + (size_t)g_list[base + mm] * K; }
        else                { int mm = (m < cnt) ? m : 0; aptr[i] = A + (size_t)(base + mm) * K; }
        aptr[i] += (tid & 7) * 8;
    }
    const int lbrow = tid >> 4;
    const uint32_t dstB = (uint32_t)(lbrow * ROWPAD_B + (tid & 15) * 16);
    const __half* bptr[4];
#pragma unroll
    for (int i = 0; i < 4; i++)
        bptr[i] = B + (size_t)(lbrow + 16 * i) * ldn + n0 + (tid & 15) * 8;

    const int S = K >> 6;
    auto issue = [&](int s) {
        uint32_t st = sbase + (uint32_t)((s % 3) * STAGE_E);
#pragma unroll
        for (int i = 0; i < 4; i++)
            CP_ASYNC16(st + dstA + (uint32_t)(32 * i * ROWPAD_A), (const void*)(aptr[i] + s * 64));
#pragma unroll
        for (int i = 0; i < 4; i++)
            CP_ASYNC16(st + TILE_A + dstB + (uint32_t)(16 * i * ROWPAD_B), (const void*)(bptr[i] + (size_t)s * 64 * ldn));
        CP_COMMIT();
    };
    issue(0);
    if (S > 1) issue(1);

    const int wm0 = (wid >> 1) * 32;
    const int wn0 = (wid & 1) * 64;
    const int arow_l = (lane & 7) + ((lane >> 3) & 1) * 8;
    const int acol_l = (lane >> 4) * 8;
    const int bkrow_l = (lane & 7) + ((lane >> 3) & 1) * 8;
    const int bncol_l = (lane >> 4) * 8;

    float acc[2][8][4];
#pragma unroll
    for (int i = 0; i < 2; i++)
#pragma unroll
        for (int j = 0; j < 8; j++)
#pragma unroll
            for (int q = 0; q < 4; q++) acc[i][j][q] = 0.f;

    for (int s = 0; s < S; s++) {
        if (s + 1 < S) cp_wait<1>(); else cp_wait<0>();
        __syncthreads();
        if (s + 2 < S) issue(s + 2);

        const uint32_t st = sbase + (uint32_t)((s % 3) * STAGE_E);
        const uint32_t sA = st, sB = st + TILE_A;
#pragma unroll
        for (int ks = 0; ks < 4; ks++) {
            const int k0 = ks * 16;
            uint32_t a[2][4], b[4][4];
#pragma unroll
            for (int mf = 0; mf < 2; mf++)
                ldsm4(a[mf][0], a[mf][1], a[mf][2], a[mf][3],
                      sA + (uint32_t)((wm0 + mf * 16 + arow_l) * ROWPAD_A + (k0 + acol_l) * 2));
#pragma unroll
            for (int p = 0; p < 4; p++)
                ldsm4t(b[p][0], b[p][1], b[p][2], b[p][3],
                       sB + (uint32_t)((k0 + bkrow_l) * ROWPAD_B + (wn0 + p * 16 + bncol_l) * 2));
#pragma unroll
            for (int mf = 0; mf < 2; mf++)
#pragma unroll
                for (int nf = 0; nf < 8; nf++)
                    mma16816(acc[mf][nf], a[mf], &b[nf >> 1][(nf & 1) * 2]);
        }
    }

    // ---- epilogue ----
    const int tr = lane >> 2, tc = (lane & 3) * 2;
#pragma unroll
    for (int mf = 0; mf < 2; mf++) {
#pragma unroll
        for (int half_ = 0; half_ < 2; half_++) {
            const int m = m0 + wm0 + mf * 16 + tr + half_ * 8;
            bool ok = (MODE == 0) || (m < cnt);
            if (!ok) continue;
            int orow = m; float wgt = 1.f;
            int s0 = 0, s1 = 0;
            if (MODE == 1) orow = base + m;
            if (MODE == 2) {
                if (OUT == 3) { orow = base + m; wgt = g_wlist[base + m]; }
                else          { orow = g_list[base + m]; wgt = g_wlist[base + m]; }
            }
            if (OUT == 4) { s0 = g_slot[2 * m]; s1 = g_slot[2 * m + 1]; }
#pragma unroll
            for (int nf = 0; nf < 8; nf++) {
                const int c = n0 + wn0 + nf * 8 + tc;
                float v0 = acc[mf][nf][half_ * 2 + 0] + bias[c];
                float v1 = acc[mf][nf][half_ * 2 + 1] + bias[c + 1];
                if (ACT == 1) { v0 = gelu_erf(v0);  v1 = gelu_erf(v1); }
                if (ACT == 2) { v0 = gelu_tanh(v0); v1 = gelu_tanh(v1); }
                if (OUT == 0) {
                    float2 w2; w2.x = v0; w2.y = v1;
                    *reinterpret_cast<float2*>((float*)Cv + (size_t)orow * ldn + c) = w2;
                } else if (OUT == 1) {
                    *reinterpret_cast<__half2*>((__half*)Cv + (size_t)orow * ldn + c) =
                        __halves2half2(__float2half_rn(v0), __float2half_rn(v1));
                } else if (OUT == 3) {
                    *reinterpret_cast<__half2*>((__half*)Cv + (size_t)orow * ldn + c) =
                        __halves2half2(__float2half_rn(wgt * v0), __float2half_rn(wgt * v1));
                } else { // OUT == 4: fused routed combine (ho fp16)
                    float2 r0 = __half22float2(*reinterpret_cast<const __half2*>(g_ho + (size_t)s0 * DIMD + c));
                    float2 r1 = __half22float2(*reinterpret_cast<const __half2*>(g_ho + (size_t)s1 * DIMD + c));
                    float2 w2; w2.x = v0 + r0.x + r1.x; w2.y = v1 + r0.y + r1.y;
                    *reinterpret_cast<float2*>((float*)Cv + (size_t)orow * ldn + c) = w2;
                }
            }
        }
    }
}

// ---------------- fp32 repair SGEMM: gathered rows (g_fixList), gelu_erf, compact out ----------------
__global__ __launch_bounds__(256, 2)
void sgemm_fix(const float* __restrict__ A, const float* __restrict__ B,
               const float* __restrict__ bias, float* __restrict__ C)
{
    const int cnt = g_fixCnt;
    const int m0 = blockIdx.x * 128;
    if (m0 >= cnt) return;
    const int n0 = blockIdx.y * 128;
    const int K = DIMD, N = DIMH;

    __shared__ float As[8][128];
    __shared__ float Bs[8][128];
    const int tid = threadIdx.x;
    const int aRow = tid >> 1, aCol = (tid & 1) * 4;
    const int bRow = tid >> 5, bCol = (tid & 31) * 4;

    int mA = m0 + aRow;
    int mm = (mA < cnt) ? mA : 0;
    const float* Arow = A + (size_t)g_fixList[mm] * K;
    const float* Bp = B + (size_t)bRow * N + n0 + bCol;

    const int ty = tid >> 4, tx = tid & 15;
    float acc[8][8];
#pragma unroll
    for (int i = 0; i < 8; i++)
#pragma unroll
        for (int j = 0; j < 8; j++) acc[i][j] = 0.f;

    for (int k0 = 0; k0 < K; k0 += 8) {
        float4 av = *reinterpret_cast<const float4*>(Arow + k0 + aCol);
        As[aCol + 0][aRow] = av.x; As[aCol + 1][aRow] = av.y;
        As[aCol + 2][aRow] = av.z; As[aCol + 3][aRow] = av.w;
        *reinterpret_cast<float4*>(&Bs[bRow][bCol]) = *reinterpret_cast<const float4*>(Bp + (size_t)k0 * N);
        __syncthreads();
#pragma unroll
        for (int kk = 0; kk < 8; kk++) {
            float4 a0 = *reinterpret_cast<const float4*>(&As[kk][ty * 8]);
            float4 a1 = *reinterpret_cast<const float4*>(&As[kk][ty * 8 + 4]);
            float4 b0 = *reinterpret_cast<const float4*>(&Bs[kk][tx * 8]);
            float4 b1 = *reinterpret_cast<const float4*>(&Bs[kk][tx * 8 + 4]);
            float a[8] = {a0.x, a0.y, a0.z, a0.w, a1.x, a1.y, a1.z, a1.w};
            float b[8] = {b0.x, b0.y, b0.z, b0.w, b1.x, b1.y, b1.z, b1.w};
#pragma unroll
            for (int i = 0; i < 8; i++)
#pragma unroll
                for (int j = 0; j < 8; j++)
                    acc[i][j] = fmaf(a[i], b[j], acc[i][j]);
        }
        __syncthreads();
    }
    const int cRow0 = m0 + ty * 8, cCol0 = n0 + tx * 8;
#pragma unroll
    for (int i = 0; i < 8; i++) {
        int m = cRow0 + i;
        if (m >= cnt) continue;
#pragma unroll
        for (int j = 0; j < 8; j++)
            C[(size_t)m * N + cCol0 + j] = gelu_erf(acc[i][j] + bias[cCol0 + j]);
    }
}

// ---------------- logits: 4 tokens/block (R15 verified) ----------------
__global__ void logits_topk(const float* __restrict__ h1,
                            const float* __restrict__ gw2,
                            const float* __restrict__ gb2)
{
    __shared__ float red[8][TPB_LOG][NEXP];
    const int t0 = blockIdx.x * TPB_LOG;
    float acc[TPB_LOG][NEXP];
#pragma unroll
    for (int tt = 0; tt < TPB_LOG; tt++)
#pragma unroll
        for (int j = 0; j < NEXP; j++) acc[tt][j] = 0.f;

    for (int i = threadIdx.x; i < DIMH; i += 256) {
        float4 w0 = *reinterpret_cast<const float4*>(gw2 + (size_t)i * NEXP);
        float4 w1 = *reinterpret_cast<const float4*>(gw2 + (size_t)i * NEXP + 4);
#pragma unroll
        for (int tt = 0; tt < TPB_LOG; tt++) {
            float h = h1[(size_t)(t0 + tt) * DIMH + i];
            acc[tt][0] = fmaf(h, w0.x, acc[tt][0]); acc[tt][1] = fmaf(h, w0.y, acc[tt][1]);
            acc[tt][2] = fmaf(h, w0.z, acc[tt][2]); acc[tt][3] = fmaf(h, w0.w, acc[tt][3]);
            acc[tt][4] = fmaf(h, w1.x, acc[tt][4]); acc[tt][5] = fmaf(h, w1.y, acc[tt][5]);
            acc[tt][6] = fmaf(h, w1.z, acc[tt][6]); acc[tt][7] = fmaf(h, w1.w, acc[tt][7]);
        }
    }
    const int lane = threadIdx.x & 31, wid = threadIdx.x >> 5;
#pragma unroll
    for (int tt = 0; tt < TPB_LOG; tt++)
#pragma unroll
        for (int j = 0; j < NEXP; j++)
#pragma unroll
            for (int o = 16; o > 0; o >>= 1)
                acc[tt][j] += __shfl_down_sync(0xffffffffu, acc[tt][j], o);
    if (lane == 0) {
#pragma unroll
        for (int tt = 0; tt < TPB_LOG; tt++)
#pragma unroll
            for (int j = 0; j < NEXP; j++) red[wid][tt][j] = acc[tt][j];
    }
    __syncthreads();
    if (threadIdx.x < TPB_LOG) {
        const int tt = threadIdx.x;
        const int t = t0 + tt;
        float l[NEXP];
#pragma unroll
        for (int j = 0; j < NEXP; j++) {
            l[j] = gb2[j];
#pragma unroll
            for (int w = 0; w < 8; w++) l[j] += red[w][tt][j];
        }
        float mx = l[0];
#pragma unroll
        for (int j = 1; j < NEXP; j++) mx = fmaxf(mx, l[j]);
        float p[NEXP], s = 0.f;
#pragma unroll
        for (int j = 0; j < NEXP; j++) { p[j] = expf(l[j] - mx); s += p[j]; }
        float inv = 1.0f / s;
#pragma unroll
        for (int j = 0; j < NEXP; j++) p[j] *= inv;
        int i0 = 0;
#pragma unroll
        for (int j = 1; j < NEXP; j++) if (p[j] > p[i0]) i0 = j;
        int i1 = (i0 == 0) ? 1 : 0;
#pragma unroll
        for (int j = 0; j < NEXP; j++) if (j != i0 && p[j] > p[i1]) i1 = j;
        g_topk_idx[t * 2 + 0] = i0;  g_topk_w[t * 2 + 0] = p[i0];
        g_topk_idx[t * 2 + 1] = i1;  g_topk_w[t * 2 + 1] = p[i1];
        float p2 = -1.f;
#pragma unroll
        for (int j = 0; j < NEXP; j++)
            if (j != i0 && j != i1 && p[j] > p2) p2 = p[j];
        if (p[i1] - p2 < MARGIN_TAU) {
            int ix = atomicAdd(&g_fixCnt, 1);
            g_fixList[ix] = t;
        }
    }
}

// ---------------- repair: exact fp32 logits for flagged tokens ----------------
__global__ void repair_logits(const float* __restrict__ hf,
                              const float* __restrict__ gw2,
                              const float* __restrict__ gb2)
{
    __shared__ float red[8][NEXP];
    for (int r = blockIdx.x; r < g_fixCnt; r += gridDim.x) {
        const int t = g_fixList[r];
        const float* hrow = hf + (size_t)r * DIMH;
        float acc[NEXP];
#pragma unroll
        for (int j = 0; j < NEXP; j++) acc[j] = 0.f;
        for (int i = threadIdx.x; i < DIMH; i += 256) {
            float h = hrow[i];
            float4 w0 = *reinterpret_cast<const float4*>(gw2 + (size_t)i * NEXP);
            float4 w1 = *reinterpret_cast<const float4*>(gw2 + (size_t)i * NEXP + 4);
            acc[0] = fmaf(h, w0.x, acc[0]); acc[1] = fmaf(h, w0.y, acc[1]);
            acc[2] = fmaf(h, w0.z, acc[2]); acc[3] = fmaf(h, w0.w, acc[3]);
            acc[4] = fmaf(h, w1.x, acc[4]); acc[5] = fmaf(h, w1.y, acc[5]);
            acc[6] = fmaf(h, w1.z, acc[6]); acc[7] = fmaf(h, w1.w, acc[7]);
        }
        const int lane = threadIdx.x & 31, wd = threadIdx.x >> 5;
#pragma unroll
        for (int j = 0; j < NEXP; j++)
#pragma unroll
            for (int o = 16; o > 0; o >>= 1)
                acc[j] += __shfl_down_sync(0xffffffffu, acc[j], o);
        if (lane == 0) {
#pragma unroll
            for (int j = 0; j < NEXP; j++) red[wd][j] = acc[j];
        }
        __syncthreads();
        if (threadIdx.x == 0) {
            float l[NEXP];
#pragma unroll
            for (int j = 0; j < NEXP; j++) {
                l[j] = gb2[j];
#pragma unroll
                for (int w = 0; w < 8; w++) l[j] += red[w][j];
            }
            float mx = l[0];
#pragma unroll
            for (int j = 1; j < NEXP; j++) mx = fmaxf(mx, l[j]);
            float p[NEXP], s = 0.f;
#pragma unroll
            for (int j = 0; j < NEXP; j++) { p[j] = expf(l[j] - mx); s += p[j]; }
            float inv = 1.0f / s;
#pragma unroll
            for (int j = 0; j < NEXP; j++) p[j] *= inv;
            int i0 = 0;
#pragma unroll
            for (int j = 1; j < NEXP; j++) if (p[j] > p[i0]) i0 = j;
            int i1 = (i0 == 0) ? 1 : 0;
#pragma unroll
            for (int j = 0; j < NEXP; j++) if (j != i0 && p[j] > p[i1]) i1 = j;
            g_topk_idx[t * 2 + 0] = i0;  g_topk_w[t * 2 + 0] = p[i0];
            g_topk_idx[t * 2 + 1] = i1;  g_topk_w[t * 2 + 1] = p[i1];
        }
        __syncthreads();
    }
}

// ---------------- deterministic dispatch ----------------
__global__ void dispatch_count() {
    __shared__ int scnt[NEXP];
    if (threadIdx.x < NEXP) scnt[threadIdx.x] = 0;
    __syncthreads();
    int item = blockIdx.x * 256 + threadIdx.x;
    atomicAdd(&scnt[g_topk_idx[item]], 1);
    __syncthreads();
    if (threadIdx.x < NEXP) g_blockCnt[blockIdx.x * NEXP + threadIdx.x] = scnt[threadIdx.x];
}
// MLP-prefetch scan (R13 verified)
__global__ void dispatch_scan() {
    int e = threadIdx.x;
    if (e < NEXP) {
        int v[NBLK_DISP];
#pragma unroll
        for (int b = 0; b < NBLK_DISP; b++)
            v[b] = g_blockCnt[b * NEXP + e];
        int off = 0;
#pragma unroll
        for (int b = 0; b < NBLK_DISP; b++) {
            g_blockOff[b * NEXP + e] = off;
            off += v[b];
        }
        g_cnt[e] = off;
    }
    __syncthreads();
    if (threadIdx.x == 0) {
        int base = 0, mb = 0;
        for (int i = 0; i < NEXP; i++) {
            g_base[i] = base; base += g_cnt[i];
            g_mblkBase[i] = mb; mb += (g_cnt[i] + 127) >> 7;
        }
        g_mblkBase[NEXP] = mb;
    }
}
__global__ void dispatch_write() {
    __shared__ int se[256];
    const int i = threadIdx.x;
    const int item = blockIdx.x * 256 + i;
    const int e = g_topk_idx[item];
    se[i] = e;
    __syncthreads();
    int rank = 0;
    for (int j = 0; j < i; j++) rank += (se[j] == e);
    int pos = g_base[e] + g_blockOff[blockIdx.x * NEXP + e] + rank;
    g_list[pos]  = item >> 1;
    g_wlist[pos] = g_topk_w[item];
    g_slot[item] = pos;
}

// ---------------- launch ----------------
extern "C" void kernel_launch(void* const* d_in, const int* in_sizes, int n_in,
                              void* d_out, int out_size)
{
    const float* x   = (const float*)d_in[0];
    const float* gw1 = (const float*)d_in[2];
    const float* gb1 = (const float*)d_in[3];
    const float* gw2 = (const float*)d_in[4];
    const float* gb2 = (const float*)d_in[5];
    const float* We1 = (const float*)d_in[6];
    const float* be1 = (const float*)d_in[7];
    const float* We2 = (const float*)d_in[8];
    const float* be2 = (const float*)d_in[9];
    const float* Ws1 = (const float*)d_in[10];
    const float* bs1 = (const float*)d_in[11];
    const float* Ws2 = (const float*)d_in[12];
    const float* bs2 = (const float*)d_in[13];
    float* out = (float*)d_out;

    float  *h1;
    __half *hs, *he, *ho, *xhi, *Bg1h, *Bs1h, *Bs2h, *Be1h, *Be2h;
    cudaGetSymbolAddress((void**)&h1,   g_h1);
    cudaGetSymbolAddress((void**)&hs,   g_hs);
    cudaGetSymbolAddress((void**)&he,   g_he);
    cudaGetSymbolAddress((void**)&ho,   g_ho);
    cudaGetSymbolAddress((void**)&xhi,  g_xhi);
    cudaGetSymbolAddress((void**)&Bg1h, g_Bg1h);
    cudaGetSymbolAddress((void**)&Bs1h, g_Bs1h);
    cudaGetSymbolAddress((void**)&Bs2h, g_Bs2h);
    cudaGetSymbolAddress((void**)&Be1h, g_Be1h);
    cudaGetSymbolAddress((void**)&Be2h, g_Be2h);

    cudaFuncSetAttribute(gemm_f16<0,1,0>, cudaFuncAttributeMaxDynamicSharedMemorySize, SME_BYTES);
    cudaFuncSetAttribute(gemm_f16<0,2,1>, cudaFuncAttributeMaxDynamicSharedMemorySize, SME_BYTES);
    cudaFuncSetAttribute(gemm_f16<0,0,4>, cudaFuncAttributeMaxDynamicSharedMemorySize, SME_BYTES);
    cudaFuncSetAttribute(gemm_f16<1,2,1>, cudaFuncAttributeMaxDynamicSharedMemorySize, SME_BYTES);
    cudaFuncSetAttribute(gemm_f16<2,0,3>, cudaFuncAttributeMaxDynamicSharedMemorySize, SME_BYTES);

    // side stream + fork/join events (host objects; created once; no device memory)
    static cudaStream_t s2 = nullptr;
    static cudaEvent_t evFork = nullptr, evJoin = nullptr, evFork2 = nullptr, evJoin2 = nullptr;
    if (s2 == nullptr) {
        cudaStreamCreateWithFlags(&s2, cudaStreamNonBlocking);
        cudaEventCreateWithFlags(&evFork,  cudaEventDisableTiming);
        cudaEventCreateWithFlags(&evJoin,  cudaEventDisableTiming);
        cudaEventCreateWithFlags(&evFork2, cudaEventDisableTiming);
        cudaEventCreateWithFlags(&evJoin2, cudaEventDisableTiming);
    }

    // ---- main stream: x convert (also resets fixCnt) ----
    cvt_hi<<<(T_TOK * DIMD / 8 + 255) / 256, 256>>>(x, xhi, T_TOK * DIMD / 8);

    // ---- fork #1: big expert-weight converts on s2 ----
    cudaEventRecord(evFork, 0);
    cudaStreamWaitEvent(s2, evFork, 0);
    cvt_w<<<(NEXP * DIMD * DIMH / 8 + 255) / 256, 256, 0, s2>>>(We1, Be1h, NEXP * DIMD * DIMH / 8);
    cvt_w<<<(NEXP * DIMH * DIMD / 8 + 255) / 256, 256, 0, s2>>>(We2, Be2h, NEXP * DIMH * DIMD / 8);
    cudaEventRecord(evJoin, s2);

    // ---- main stream: gate GEMM + shared-expert weight converts ----
    cvt_w<<<(DIMD * DIMH / 8 + 255) / 256, 256>>>(gw1, Bg1h, DIMD * DIMH / 8);
    gemm_f16<0,1,0><<<dim3(T_TOK / 128, DIMH / 128), 256, SME_BYTES>>>(xhi, Bg1h, gb1, h1, DIMD, DIMH);
    cvt_w<<<(DIMD * DIMH / 8 + 255) / 256, 256>>>(Ws1, Bs1h, DIMD * DIMH / 8);
    cvt_w<<<(DIMH * DIMD / 8 + 255) / 256, 256>>>(Ws2, Bs2h, DIMH * DIMD / 8);

    // ---- fork #2: shared-expert GEMM1 on s2 (fills routing-phase idle + GEMM wave tails) ----
    cudaEventRecord(evFork2, 0);
    cudaStreamWaitEvent(s2, evFork2, 0);                // s2: after We converts, run shared1
    gemm_f16<0,2,1><<<dim3(T_TOK / 128, DIMH / 128), 256, SME_BYTES, s2>>>(xhi, Bs1h, bs1, hs, DIMD, DIMH);
    cudaEventRecord(evJoin2, s2);

    // ---- main stream: routing + margin repair + dispatch ----
    logits_topk<<<T_TOK / TPB_LOG, 256>>>(h1, gw2, gb2);
    sgemm_fix<<<dim3(T_TOK / 128, DIMH / 128), 256>>>(x, gw1, gb1, h1);
    repair_logits<<<512, 256>>>(h1, gw2, gb2);
    dispatch_count<<<NBLK_DISP, 256>>>();
    dispatch_scan<<<1, 32>>>();
    dispatch_write<<<NBLK_DISP, 256>>>();

    // ---- routed experts (need Be1h/Be2h from fork #1) ----
    cudaStreamWaitEvent(0, evJoin, 0);
    gemm_f16<1,2,1><<<dim3(136, DIMH / 128), 256, SME_BYTES>>>(xhi, Be1h, be1, he, DIMD, DIMH);
    gemm_f16<2,0,3><<<dim3(136, DIMD / 128), 256, SME_BYTES>>>(he,  Be2h, be2, ho, DIMH, DIMD);

    // ---- shared GEMM2 (needs hs from fork #2 and ho) with fused routed combine ----
    cudaStreamWaitEvent(0, evJoin2, 0);
    gemm_f16<0,0,4><<<dim3(T_TOK / 128, DIMD / 128), 256, SME_BYTES>>>(hs, Bs2h, bs2, out, DIMH, DIMD);
}